// round 4
// baseline (speedup 1.0000x reference)
#include <cuda_runtime.h>
#include <math.h>

#define Sx 512
#define Bx 256
#define Ix 256
#define Hx 1024
#define SWx 256
#define SDx 100
#define KTOT 1536        // I + SW + H
#define GRID 128
#define NTHR 256
#define KC 32
#define NCHUNK (KTOT / KC)   // 48

// ---------------- persistent device state ----------------
__device__ float g_c[(size_t)Bx * Hx];
__device__ float g_stack[2][(size_t)Bx * SDx * SWx];
__device__ float g_d[(size_t)Bx * SWx];
__device__ float g_ctl[Bx * 4];
__device__ unsigned g_bar_count = 0;
__device__ unsigned g_bar_gen = 0;

// ---------------- helpers ----------------
__device__ __forceinline__ float sigf(float x) { return 1.0f / (1.0f + expf(-x)); }

__device__ __forceinline__ unsigned f2tf(float x) {
    unsigned r;
    asm("cvt.rna.tf32.f32 %0, %1;" : "=r"(r) : "f"(x));
    return r;
}

__device__ __forceinline__ void mma_tf32(float* c, const unsigned* a, const unsigned* b) {
    asm volatile(
        "mma.sync.aligned.m16n8k8.row.col.f32.tf32.tf32.f32 "
        "{%0,%1,%2,%3},{%4,%5,%6,%7},{%8,%9},{%0,%1,%2,%3};"
        : "+f"(c[0]), "+f"(c[1]), "+f"(c[2]), "+f"(c[3])
        : "r"(a[0]), "r"(a[1]), "r"(a[2]), "r"(a[3]), "r"(b[0]), "r"(b[1]));
}

__device__ __forceinline__ void gridbar() {
    __syncthreads();
    if (threadIdx.x == 0) {
        __threadfence();
        unsigned old = atomicAdd(&g_bar_count, 1u);
        if ((old % GRID) == (GRID - 1u)) {
            atomicAdd(&g_bar_gen, 1u);
        } else {
            unsigned target = old / GRID + 1u;
            while ((int)(*(volatile unsigned*)&g_bar_gen - target) < 0) {
                __nanosleep(32);
            }
        }
        __threadfence();
    }
    __syncthreads();
}

// ---------------- shared memory (phase union) ----------------
struct SmemP1 { float A[128 * 36]; float W[64 * 36]; };
struct SmemP2 { float hs[64 * 33]; float dws[16 * 68]; };
union Smem {
    SmemP1 p1;
    float gates[128 * 68];
    SmemP2 p2;
};

__global__ void __launch_bounds__(NTHR)
stackrnn_kernel(const float* __restrict__ x, const float* __restrict__ h0,
                const float* __restrict__ c0, const float* __restrict__ stack0,
                const float* __restrict__ W_ih, const float* __restrict__ W_hh,
                const float* __restrict__ b_ih, const float* __restrict__ b_hh,
                const float* __restrict__ A_w, const float* __restrict__ A_b,
                const float* __restrict__ D_w, const float* __restrict__ D_b,
                float* __restrict__ out) {
    __shared__ Smem sm;
    const int tid = threadIdx.x;
    const int cta = blockIdx.x;

    float* outs = out;                                    // (S,B,H)
    float* out_hn = out + (size_t)Sx * Bx * Hx;           // (1,B,H)
    float* out_cn = out_hn + (size_t)Bx * Hx;             // (1,B,H)
    float* out_st = out_cn + (size_t)Bx * Hx;             // (B,SD,SW)

    // ---- P1 mapping: CTA tile = 128 batches x (16 hidden units * 4 gates) ----
    const int mt = cta & 1;          // M tile (batch half)
    const int nt = cta >> 1;         // 64 hidden-unit tiles
    const int u0 = nt * 16;
    const int row0 = mt * 128;
    const int warp = tid >> 5, lane = tid & 31;
    const int wm = warp & 3, wn = warp >> 2;       // 4x2 warp grid over 128x64
    const int gi = lane >> 2, tg = lane & 3;
    const int m_base = wm * 32, n_base = wn * 32;

    for (int t = 0; t < Sx; ++t) {
        const float* hprev = (t == 0) ? h0 : (outs + (size_t)(t - 1) * Bx * Hx);
        const float* stk_r = (t == 0) ? stack0 : g_stack[t & 1];

        // ======================= P1: gates GEMM + fused LSTM =======================
        float acc[2][4][4];
#pragma unroll
        for (int a = 0; a < 2; a++)
#pragma unroll
            for (int b = 0; b < 4; b++)
#pragma unroll
                for (int c = 0; c < 4; c++) acc[a][b][c] = 0.f;

        float4 aR[4];
        float4 wR[2];

        auto loadA = [&](int k0) {
#pragma unroll
            for (int ii = 0; ii < 4; ii++) {
                int e = tid + ii * NTHR;
                int arow = e >> 3, c4 = e & 7;
                int k = k0 + c4 * 4;
                int b = row0 + arow;
                const float* p;
                if (k0 < Ix)
                    p = x + (size_t)t * Bx * Ix + (size_t)b * Ix + k;
                else if (k0 < Ix + SWx)
                    p = stk_r + (size_t)b * SDx * SWx + (k - Ix);
                else
                    p = hprev + (size_t)b * Hx + (k - (Ix + SWx));
                aR[ii] = __ldcg((const float4*)p);
            }
        };
        auto loadW = [&](int k0) {
#pragma unroll
            for (int ii = 0; ii < 2; ii++) {
                int e = tid + ii * NTHR;
                int n = e >> 3, c4 = e & 7;
                int k = k0 + c4 * 4;
                int r = ((n >> 4) << 10) + u0 + (n & 15);
                const float* p = (k < Ix + SWx)
                                     ? (W_ih + (size_t)r * (Ix + SWx) + k)
                                     : (W_hh + (size_t)r * Hx + (k - (Ix + SWx)));
                wR[ii] = __ldg((const float4*)p);
            }
        };
        auto storeSm = [&]() {
#pragma unroll
            for (int ii = 0; ii < 4; ii++) {
                int e = tid + ii * NTHR;
                int arow = e >> 3, c4 = e & 7;
                float* d = &sm.p1.A[arow * 36 + c4 * 4];
                d[0] = __uint_as_float(f2tf(aR[ii].x));
                d[1] = __uint_as_float(f2tf(aR[ii].y));
                d[2] = __uint_as_float(f2tf(aR[ii].z));
                d[3] = __uint_as_float(f2tf(aR[ii].w));
            }
#pragma unroll
            for (int ii = 0; ii < 2; ii++) {
                int e = tid + ii * NTHR;
                int n = e >> 3, c4 = e & 7;
                float* d = &sm.p1.W[n * 36 + c4 * 4];
                d[0] = __uint_as_float(f2tf(wR[ii].x));
                d[1] = __uint_as_float(f2tf(wR[ii].y));
                d[2] = __uint_as_float(f2tf(wR[ii].z));
                d[3] = __uint_as_float(f2tf(wR[ii].w));
            }
        };

        loadA(0);
        loadW(0);
        for (int kc = 0; kc < NCHUNK; kc++) {
            __syncthreads();   // smem free (prev chunk's mma done)
            storeSm();
            __syncthreads();   // smem visible
            if (kc + 1 < NCHUNK) { loadA((kc + 1) * KC); loadW((kc + 1) * KC); }
#pragma unroll
            for (int kk = 0; kk < 4; kk++) {
                const int kb = kk * 8;
                unsigned afr[2][4], bfr[4][2];
#pragma unroll
                for (int mi = 0; mi < 2; mi++) {
                    int r0 = m_base + mi * 16 + gi;
                    afr[mi][0] = __float_as_uint(sm.p1.A[r0 * 36 + kb + tg]);
                    afr[mi][1] = __float_as_uint(sm.p1.A[(r0 + 8) * 36 + kb + tg]);
                    afr[mi][2] = __float_as_uint(sm.p1.A[r0 * 36 + kb + 4 + tg]);
                    afr[mi][3] = __float_as_uint(sm.p1.A[(r0 + 8) * 36 + kb + 4 + tg]);
                }
#pragma unroll
                for (int ni = 0; ni < 4; ni++) {
                    int c0i = n_base + ni * 8 + gi;
                    bfr[ni][0] = __float_as_uint(sm.p1.W[c0i * 36 + kb + tg]);
                    bfr[ni][1] = __float_as_uint(sm.p1.W[c0i * 36 + kb + 4 + tg]);
                }
#pragma unroll
                for (int mi = 0; mi < 2; mi++)
#pragma unroll
                    for (int ni = 0; ni < 4; ni++) mma_tf32(acc[mi][ni], afr[mi], bfr[ni]);
            }
        }
        __syncthreads();
        // stage gates tile (128 x 64) to smem
#pragma unroll
        for (int mi = 0; mi < 2; mi++)
#pragma unroll
            for (int ni = 0; ni < 4; ni++) {
                int row = m_base + mi * 16 + gi;
                int coln = n_base + ni * 8 + tg * 2;
                sm.gates[row * 68 + coln] = acc[mi][ni][0];
                sm.gates[row * 68 + coln + 1] = acc[mi][ni][1];
                sm.gates[(row + 8) * 68 + coln] = acc[mi][ni][2];
                sm.gates[(row + 8) * 68 + coln + 1] = acc[mi][ni][3];
            }
        __syncthreads();
        // fused LSTM pointwise
#pragma unroll
        for (int ii = 0; ii < 8; ii++) {
            int e = tid + ii * NTHR;
            int arow = e >> 4, up = e & 15;
            int u = u0 + up;
            int b = row0 + arow;
            float iv = sm.gates[arow * 68 + up] + b_ih[u] + b_hh[u];
            float fv = sm.gates[arow * 68 + 16 + up] + b_ih[Hx + u] + b_hh[Hx + u];
            float gv = sm.gates[arow * 68 + 32 + up] + b_ih[2 * Hx + u] + b_hh[2 * Hx + u];
            float ov = sm.gates[arow * 68 + 48 + up] + b_ih[3 * Hx + u] + b_hh[3 * Hx + u];
            float cold = (t == 0) ? c0[(size_t)b * Hx + u] : g_c[(size_t)b * Hx + u];
            float cnew = sigf(fv) * cold + sigf(iv) * tanhf(gv);
            float hnew = sigf(ov) * tanhf(cnew);
            g_c[(size_t)b * Hx + u] = cnew;
            outs[(size_t)t * Bx * Hx + (size_t)b * Hx + u] = hnew;
        }
        gridbar();

        // ======================= P2: D-GEMM + controls softmax =======================
        {
            const int mtile = cta >> 4;    // 8 tiles of 32 batches
            const int ntile = cta & 15;    // 16 tiles of 16 cols
            const float* ht = outs + (size_t)t * Bx * Hx;
            const int xr = tid & 31, yr = tid >> 5;
            float a0 = 0.f, a1 = 0.f;
            for (int kc2 = 0; kc2 < Hx; kc2 += 64) {
#pragma unroll
                for (int ii = 0; ii < 2; ii++) {
                    int e = tid + ii * NTHR;
                    int r = e >> 4, c4 = e & 15;
                    int k = c4 * 4;
                    float4 v = __ldcg((const float4*)(ht + (size_t)(mtile * 32 + r) * Hx + kc2 + k));
                    sm.p2.hs[(k + 0) * 33 + r] = v.x;
                    sm.p2.hs[(k + 1) * 33 + r] = v.y;
                    sm.p2.hs[(k + 2) * 33 + r] = v.z;
                    sm.p2.hs[(k + 3) * 33 + r] = v.w;
                }
                {
                    int r = tid >> 4, c4 = tid & 15;
                    float4 v = __ldg((const float4*)(D_w + (size_t)(ntile * 16 + r) * Hx + kc2 + c4 * 4));
                    float* dd = &sm.p2.dws[r * 68 + c4 * 4];
                    dd[0] = v.x; dd[1] = v.y; dd[2] = v.z; dd[3] = v.w;
                }
                __syncthreads();
#pragma unroll
                for (int k = 0; k < 64; k++) {
                    float hv = sm.p2.hs[k * 33 + xr];
                    a0 += hv * sm.p2.dws[yr * 68 + k];
                    a1 += hv * sm.p2.dws[(yr + 8) * 68 + k];
                }
                __syncthreads();
            }
            int b = mtile * 32 + xr;
            int j0 = ntile * 16 + yr, j1 = j0 + 8;
            g_d[(size_t)b * SWx + j0] = tanhf(a0 + D_b[j0]);
            g_d[(size_t)b * SWx + j1] = tanhf(a1 + D_b[j1]);

            if (cta < 32) {   // controls: warp per batch
                int b2 = cta * 8 + warp;
                const float* hb = ht + (size_t)b2 * Hx;
                float s0 = 0.f, s1 = 0.f, s2 = 0.f;
                for (int k = lane; k < Hx; k += 32) {
                    float hv = __ldcg(hb + k);
                    s0 += hv * A_w[k];
                    s1 += hv * A_w[Hx + k];
                    s2 += hv * A_w[2 * Hx + k];
                }
#pragma unroll
                for (int o = 16; o > 0; o >>= 1) {
                    s0 += __shfl_xor_sync(0xffffffffu, s0, o);
                    s1 += __shfl_xor_sync(0xffffffffu, s1, o);
                    s2 += __shfl_xor_sync(0xffffffffu, s2, o);
                }
                if (lane == 0) {
                    s0 += A_b[0]; s1 += A_b[1]; s2 += A_b[2];
                    float mx = fmaxf(s0, fmaxf(s1, s2));
                    float e0 = expf(s0 - mx), e1 = expf(s1 - mx), e2 = expf(s2 - mx);
                    float inv = 1.f / (e0 + e1 + e2);
                    g_ctl[b2 * 4 + 0] = e0 * inv;
                    g_ctl[b2 * 4 + 1] = e1 * inv;
                    g_ctl[b2 * 4 + 2] = e2 * inv;
                }
            }
        }
        gridbar();

        // ======================= P3: stack blend (+ final copies) =======================
        {
            float* wst = (t == Sx - 1) ? out_st : g_stack[(t + 1) & 1];
#pragma unroll
            for (int bi = 0; bi < 2; bi++) {
                int b = cta * 2 + bi;
                float push = __ldcg(&g_ctl[b * 4 + 0]);
                float pop = __ldcg(&g_ctl[b * 4 + 1]);
                float noop = __ldcg(&g_ctl[b * 4 + 2]);
                float dv = __ldcg(&g_d[(size_t)b * SWx + tid]);
                const float* sp = stk_r + (size_t)b * SDx * SWx + tid;
                float* dp = wst + (size_t)b * SDx * SWx + tid;
                float prev = dv;
                float cur = __ldcg(sp);
#pragma unroll 5
                for (int i = 0; i < SDx; i++) {
                    float nxt = (i < SDx - 1) ? __ldcg(sp + (size_t)(i + 1) * SWx) : 0.f;
                    dp[(size_t)i * SWx] = noop * cur + push * prev + pop * nxt;
                    prev = cur;
                    cur = nxt;
                }
            }
            if (t == Sx - 1) {
                const float* hlast = outs + (size_t)(Sx - 1) * Bx * Hx;
                for (int idx = cta * NTHR + tid; idx < Bx * Hx; idx += GRID * NTHR) {
                    out_hn[idx] = __ldcg(hlast + idx);
                    out_cn[idx] = __ldcg(&g_c[idx]);
                }
            }
        }
        gridbar();
    }
}

extern "C" void kernel_launch(void* const* d_in, const int* in_sizes, int n_in,
                              void* d_out, int out_size) {
    (void)in_sizes; (void)n_in; (void)out_size;
    stackrnn_kernel<<<GRID, NTHR>>>(
        (const float*)d_in[0], (const float*)d_in[1], (const float*)d_in[2],
        (const float*)d_in[3], (const float*)d_in[4], (const float*)d_in[5],
        (const float*)d_in[6], (const float*)d_in[7], (const float*)d_in[8],
        (const float*)d_in[9], (const float*)d_in[10], (const float*)d_in[11],
        (float*)d_out);
}

// round 5
// speedup vs baseline: 1.1589x; 1.1589x over previous
#include <cuda_runtime.h>
#include <math.h>

#define Sx 512
#define Bx 256
#define Ix 256
#define Hx 1024
#define SWx 256
#define SDx 100
#define KTOT 1536        // I + SW + H
#define GRID 128
#define NTHR 256
#define KC 32
#define NCHUNK (KTOT / KC)   // 48

// ---------------- persistent device state ----------------
__device__ float g_c[(size_t)Bx * Hx];
__device__ float g_stack[2][(size_t)Bx * SDx * SWx];
__device__ float g_d[(size_t)Bx * SWx];
__device__ float g_ctl[Bx * 4];
__device__ unsigned g_bar_count = 0;
__device__ unsigned g_bar_gen = 0;

// ---------------- helpers ----------------
__device__ __forceinline__ float sigf(float x) { return 1.0f / (1.0f + expf(-x)); }

__device__ __forceinline__ unsigned f2tf(float x) {
    unsigned r;
    asm("cvt.rna.tf32.f32 %0, %1;" : "=r"(r) : "f"(x));
    return r;
}

__device__ __forceinline__ void mma_tf32(float* c, const unsigned* a, const unsigned* b) {
    asm volatile(
        "mma.sync.aligned.m16n8k8.row.col.f32.tf32.tf32.f32 "
        "{%0,%1,%2,%3},{%4,%5,%6,%7},{%8,%9},{%0,%1,%2,%3};"
        : "+f"(c[0]), "+f"(c[1]), "+f"(c[2]), "+f"(c[3])
        : "r"(a[0]), "r"(a[1]), "r"(a[2]), "r"(a[3]), "r"(b[0]), "r"(b[1]));
}

__device__ __forceinline__ void gridbar() {
    __syncthreads();
    if (threadIdx.x == 0) {
        __threadfence();
        unsigned old = atomicAdd(&g_bar_count, 1u);
        if ((old % GRID) == (GRID - 1u)) {
            atomicAdd(&g_bar_gen, 1u);
        } else {
            unsigned target = old / GRID + 1u;
            while ((int)(*(volatile unsigned*)&g_bar_gen - target) < 0) {
                __nanosleep(32);
            }
        }
        __threadfence();
    }
    __syncthreads();
}

// ---------------- shared memory (phase union) ----------------
struct SmemP1 { float A[128 * 36]; float W[64 * 36]; };
struct SmemP2 { float hs[64 * 33]; float dws[16 * 68]; };
union Smem {
    SmemP1 p1;
    float gates[128 * 68];
    SmemP2 p2;
};

__global__ void __launch_bounds__(NTHR)
stackrnn_kernel(const float* __restrict__ x, const float* __restrict__ h0,
                const float* __restrict__ c0, const float* __restrict__ stack0,
                const float* __restrict__ W_ih, const float* __restrict__ W_hh,
                const float* __restrict__ b_ih, const float* __restrict__ b_hh,
                const float* __restrict__ A_w, const float* __restrict__ A_b,
                const float* __restrict__ D_w, const float* __restrict__ D_b,
                float* __restrict__ out) {
    __shared__ Smem sm;
    const int tid = threadIdx.x;
    const int cta = blockIdx.x;

    float* outs = out;                                    // (S,B,H)
    float* out_hn = out + (size_t)Sx * Bx * Hx;           // (1,B,H)
    float* out_cn = out_hn + (size_t)Bx * Hx;             // (1,B,H)
    float* out_st = out_cn + (size_t)Bx * Hx;             // (B,SD,SW)

    // ---- P1 mapping: CTA tile = 128 batches x (16 hidden units * 4 gates) ----
    const int mt = cta & 1;          // M tile (batch half)
    const int nt = cta >> 1;         // 64 hidden-unit tiles
    const int u0 = nt * 16;
    const int row0 = mt * 128;
    const int warp = tid >> 5, lane = tid & 31;
    const int wm = warp & 3, wn = warp >> 2;       // 4x2 warp grid over 128x64
    const int gi = lane >> 2, tg = lane & 3;
    const int m_base = wm * 32, n_base = wn * 32;

    for (int t = 0; t < Sx; ++t) {
        const float* hprev = (t == 0) ? h0 : (outs + (size_t)(t - 1) * Bx * Hx);
        const float* stk_r = (t == 0) ? stack0 : g_stack[t & 1];

        // ======================= P1: gates GEMM + fused LSTM =======================
        float acc[2][4][4];
#pragma unroll
        for (int a = 0; a < 2; a++)
#pragma unroll
            for (int b = 0; b < 4; b++)
#pragma unroll
                for (int c = 0; c < 4; c++) acc[a][b][c] = 0.f;

        float4 aR[4];
        float4 wR[2];

        auto loadA = [&](int k0) {
#pragma unroll
            for (int ii = 0; ii < 4; ii++) {
                int e = tid + ii * NTHR;
                int arow = e >> 3, c4 = e & 7;
                int k = k0 + c4 * 4;
                int b = row0 + arow;
                const float* p;
                if (k0 < Ix)
                    p = x + (size_t)t * Bx * Ix + (size_t)b * Ix + k;
                else if (k0 < Ix + SWx)
                    p = stk_r + (size_t)b * SDx * SWx + (k - Ix);
                else
                    p = hprev + (size_t)b * Hx + (k - (Ix + SWx));
                aR[ii] = __ldcg((const float4*)p);
            }
        };
        auto loadW = [&](int k0) {
#pragma unroll
            for (int ii = 0; ii < 2; ii++) {
                int e = tid + ii * NTHR;
                int n = e >> 3, c4 = e & 7;
                int k = k0 + c4 * 4;
                int r = ((n >> 4) << 10) + u0 + (n & 15);
                const float* p = (k < Ix + SWx)
                                     ? (W_ih + (size_t)r * (Ix + SWx) + k)
                                     : (W_hh + (size_t)r * Hx + (k - (Ix + SWx)));
                wR[ii] = __ldg((const float4*)p);
            }
        };
        auto storeSm = [&]() {
#pragma unroll
            for (int ii = 0; ii < 4; ii++) {
                int e = tid + ii * NTHR;
                int arow = e >> 3, c4 = e & 7;
                float* d = &sm.p1.A[arow * 36 + c4 * 4];
                d[0] = __uint_as_float(f2tf(aR[ii].x));
                d[1] = __uint_as_float(f2tf(aR[ii].y));
                d[2] = __uint_as_float(f2tf(aR[ii].z));
                d[3] = __uint_as_float(f2tf(aR[ii].w));
            }
#pragma unroll
            for (int ii = 0; ii < 2; ii++) {
                int e = tid + ii * NTHR;
                int n = e >> 3, c4 = e & 7;
                float* d = &sm.p1.W[n * 36 + c4 * 4];
                d[0] = __uint_as_float(f2tf(wR[ii].x));
                d[1] = __uint_as_float(f2tf(wR[ii].y));
                d[2] = __uint_as_float(f2tf(wR[ii].z));
                d[3] = __uint_as_float(f2tf(wR[ii].w));
            }
        };

        loadA(0);
        loadW(0);
        for (int kc = 0; kc < NCHUNK; kc++) {
            __syncthreads();   // smem free (prev chunk's mma done)
            storeSm();
            __syncthreads();   // smem visible
            if (kc + 1 < NCHUNK) { loadA((kc + 1) * KC); loadW((kc + 1) * KC); }
#pragma unroll
            for (int kk = 0; kk < 4; kk++) {
                const int kb = kk * 8;
                unsigned afr[2][4], bfr[4][2];
#pragma unroll
                for (int mi = 0; mi < 2; mi++) {
                    int r0 = m_base + mi * 16 + gi;
                    afr[mi][0] = __float_as_uint(sm.p1.A[r0 * 36 + kb + tg]);
                    afr[mi][1] = __float_as_uint(sm.p1.A[(r0 + 8) * 36 + kb + tg]);
                    afr[mi][2] = __float_as_uint(sm.p1.A[r0 * 36 + kb + 4 + tg]);
                    afr[mi][3] = __float_as_uint(sm.p1.A[(r0 + 8) * 36 + kb + 4 + tg]);
                }
#pragma unroll
                for (int ni = 0; ni < 4; ni++) {
                    int c0i = n_base + ni * 8 + gi;
                    bfr[ni][0] = __float_as_uint(sm.p1.W[c0i * 36 + kb + tg]);
                    bfr[ni][1] = __float_as_uint(sm.p1.W[c0i * 36 + kb + 4 + tg]);
                }
#pragma unroll
                for (int mi = 0; mi < 2; mi++)
#pragma unroll
                    for (int ni = 0; ni < 4; ni++) mma_tf32(acc[mi][ni], afr[mi], bfr[ni]);
            }
        }
        __syncthreads();
        // stage gates tile (128 x 64) to smem
#pragma unroll
        for (int mi = 0; mi < 2; mi++)
#pragma unroll
            for (int ni = 0; ni < 4; ni++) {
                int row = m_base + mi * 16 + gi;
                int coln = n_base + ni * 8 + tg * 2;
                sm.gates[row * 68 + coln] = acc[mi][ni][0];
                sm.gates[row * 68 + coln + 1] = acc[mi][ni][1];
                sm.gates[(row + 8) * 68 + coln] = acc[mi][ni][2];
                sm.gates[(row + 8) * 68 + coln + 1] = acc[mi][ni][3];
            }
        __syncthreads();
        // fused LSTM pointwise
#pragma unroll
        for (int ii = 0; ii < 8; ii++) {
            int e = tid + ii * NTHR;
            int arow = e >> 4, up = e & 15;
            int u = u0 + up;
            int b = row0 + arow;
            float iv = sm.gates[arow * 68 + up] + b_ih[u] + b_hh[u];
            float fv = sm.gates[arow * 68 + 16 + up] + b_ih[Hx + u] + b_hh[Hx + u];
            float gv = sm.gates[arow * 68 + 32 + up] + b_ih[2 * Hx + u] + b_hh[2 * Hx + u];
            float ov = sm.gates[arow * 68 + 48 + up] + b_ih[3 * Hx + u] + b_hh[3 * Hx + u];
            float cold = (t == 0) ? c0[(size_t)b * Hx + u] : g_c[(size_t)b * Hx + u];
            float cnew = sigf(fv) * cold + sigf(iv) * tanhf(gv);
            float hnew = sigf(ov) * tanhf(cnew);
            g_c[(size_t)b * Hx + u] = cnew;
            outs[(size_t)t * Bx * Hx + (size_t)b * Hx + u] = hnew;
        }
        gridbar();

        // ======================= P2: D-GEMM + controls softmax =======================
        {
            const int mtile = cta >> 4;    // 8 tiles of 32 batches
            const int ntile = cta & 15;    // 16 tiles of 16 cols
            const float* ht = outs + (size_t)t * Bx * Hx;
            const int xr = tid & 31, yr = tid >> 5;
            float a0 = 0.f, a1 = 0.f;
            for (int kc2 = 0; kc2 < Hx; kc2 += 64) {
#pragma unroll
                for (int ii = 0; ii < 2; ii++) {
                    int e = tid + ii * NTHR;
                    int r = e >> 4, c4 = e & 15;
                    int k = c4 * 4;
                    float4 v = __ldcg((const float4*)(ht + (size_t)(mtile * 32 + r) * Hx + kc2 + k));
                    sm.p2.hs[(k + 0) * 33 + r] = v.x;
                    sm.p2.hs[(k + 1) * 33 + r] = v.y;
                    sm.p2.hs[(k + 2) * 33 + r] = v.z;
                    sm.p2.hs[(k + 3) * 33 + r] = v.w;
                }
                {
                    int r = tid >> 4, c4 = tid & 15;
                    float4 v = __ldg((const float4*)(D_w + (size_t)(ntile * 16 + r) * Hx + kc2 + c4 * 4));
                    float* dd = &sm.p2.dws[r * 68 + c4 * 4];
                    dd[0] = v.x; dd[1] = v.y; dd[2] = v.z; dd[3] = v.w;
                }
                __syncthreads();
#pragma unroll
                for (int k = 0; k < 64; k++) {
                    float hv = sm.p2.hs[k * 33 + xr];
                    a0 += hv * sm.p2.dws[yr * 68 + k];
                    a1 += hv * sm.p2.dws[(yr + 8) * 68 + k];
                }
                __syncthreads();
            }
            int b = mtile * 32 + xr;
            int j0 = ntile * 16 + yr, j1 = j0 + 8;
            g_d[(size_t)b * SWx + j0] = tanhf(a0 + D_b[j0]);
            g_d[(size_t)b * SWx + j1] = tanhf(a1 + D_b[j1]);

            if (cta < 32) {   // controls: warp per batch
                int b2 = cta * 8 + warp;
                const float* hb = ht + (size_t)b2 * Hx;
                float s0 = 0.f, s1 = 0.f, s2 = 0.f;
                for (int k = lane; k < Hx; k += 32) {
                    float hv = __ldcg(hb + k);
                    s0 += hv * A_w[k];
                    s1 += hv * A_w[Hx + k];
                    s2 += hv * A_w[2 * Hx + k];
                }
#pragma unroll
                for (int o = 16; o > 0; o >>= 1) {
                    s0 += __shfl_xor_sync(0xffffffffu, s0, o);
                    s1 += __shfl_xor_sync(0xffffffffu, s1, o);
                    s2 += __shfl_xor_sync(0xffffffffu, s2, o);
                }
                if (lane == 0) {
                    s0 += A_b[0]; s1 += A_b[1]; s2 += A_b[2];
                    float mx = fmaxf(s0, fmaxf(s1, s2));
                    float e0 = expf(s0 - mx), e1 = expf(s1 - mx), e2 = expf(s2 - mx);
                    float inv = 1.f / (e0 + e1 + e2);
                    g_ctl[b2 * 4 + 0] = e0 * inv;
                    g_ctl[b2 * 4 + 1] = e1 * inv;
                    g_ctl[b2 * 4 + 2] = e2 * inv;
                }
            }
        }
        gridbar();

        // ======================= P3: stack blend (+ final copies) =======================
        {
            float* wst = (t == Sx - 1) ? out_st : g_stack[(t + 1) & 1];
#pragma unroll
            for (int bi = 0; bi < 2; bi++) {
                int b = cta * 2 + bi;
                float push = __ldcg(&g_ctl[b * 4 + 0]);
                float pop = __ldcg(&g_ctl[b * 4 + 1]);
                float noop = __ldcg(&g_ctl[b * 4 + 2]);
                float dv = __ldcg(&g_d[(size_t)b * SWx + tid]);
                const float* sp = stk_r + (size_t)b * SDx * SWx + tid;
                float* dp = wst + (size_t)b * SDx * SWx + tid;
                float prev = dv;
                float cur = __ldcg(sp);
#pragma unroll 5
                for (int i = 0; i < SDx; i++) {
                    float nxt = (i < SDx - 1) ? __ldcg(sp + (size_t)(i + 1) * SWx) : 0.f;
                    dp[(size_t)i * SWx] = noop * cur + push * prev + pop * nxt;
                    prev = cur;
                    cur = nxt;
                }
            }
            if (t == Sx - 1) {
                const float* hlast = outs + (size_t)(Sx - 1) * Bx * Hx;
                for (int idx = cta * NTHR + tid; idx < Bx * Hx; idx += GRID * NTHR) {
                    out_hn[idx] = __ldcg(hlast + idx);
                    out_cn[idx] = __ldcg(&g_c[idx]);
                }
            }
        }
        gridbar();
    }
}

extern "C" void kernel_launch(void* const* d_in, const int* in_sizes, int n_in,
                              void* d_out, int out_size) {
    (void)in_sizes; (void)n_in; (void)out_size;
    stackrnn_kernel<<<GRID, NTHR>>>(
        (const float*)d_in[0], (const float*)d_in[1], (const float*)d_in[2],
        (const float*)d_in[3], (const float*)d_in[4], (const float*)d_in[5],
        (const float*)d_in[6], (const float*)d_in[7], (const float*)d_in[8],
        (const float*)d_in[9], (const float*)d_in[10], (const float*)d_in[11],
        (float*)d_out);
}

// round 9
// speedup vs baseline: 1.5970x; 1.3781x over previous
#include <cuda_runtime.h>
#include <math.h>
#include <stdint.h>

#define Sx 512
#define Bx 256
#define Ix 256
#define Hx 1024
#define SWx 256
#define SDx 100
#define KTOT 1536
#define GRID 128
#define NTHR 512
#define NCH1 48
#define STAGE_BYTES 27648        // A 128x36f + B 64x36f
#define DSMEM_BYTES (3 * STAGE_BYTES + 256)

// ---------------- persistent device state ----------------
__device__ float g_xr[(size_t)Sx * Bx * Ix];      // tf32-rounded x
__device__ float g_Wp[(size_t)4096 * KTOT];       // packed+rounded W (tile-ordered rows)
__device__ float g_hr[2][(size_t)Bx * Hx];        // rounded h ping-pong
__device__ float g_top[(size_t)Bx * SWx];         // rounded stack top
__device__ float g_c[(size_t)Bx * Hx];
__device__ float g_stack[2][(size_t)Bx * SDx * SWx];
__device__ float g_d[(size_t)Bx * SWx];
__device__ float g_ctl[Bx * 4];
__device__ unsigned g_bar_count = 0;
__device__ unsigned g_bar_gen = 0;

// ---------------- helpers ----------------
__device__ __forceinline__ float sigf(float x) { return 1.0f / (1.0f + expf(-x)); }
__device__ __forceinline__ float rndtf(float x) {
    unsigned r;
    asm("cvt.rna.tf32.f32 %0, %1;" : "=r"(r) : "f"(x));
    return __uint_as_float(r);
}
__device__ __forceinline__ uint32_t smem_u32(const void* p) {
    uint32_t a;
    asm("{ .reg .u64 t; cvta.to.shared.u64 t, %1; cvt.u32.u64 %0, t; }" : "=r"(a) : "l"(p));
    return a;
}
#define CP16(dst, src) \
    asm volatile("cp.async.cg.shared.global [%0], [%1], 16;" :: "r"(dst), "l"(src) : "memory")
#define CP_COMMIT() asm volatile("cp.async.commit_group;" ::: "memory")
#define CP_WAIT1()  asm volatile("cp.async.wait_group 1;" ::: "memory")

__device__ __forceinline__ void mma_tf32(float* c, const unsigned* a, const unsigned* b) {
    asm volatile(
        "mma.sync.aligned.m16n8k8.row.col.f32.tf32.tf32.f32 "
        "{%0,%1,%2,%3},{%4,%5,%6,%7},{%8,%9},{%0,%1,%2,%3};"
        : "+f"(c[0]), "+f"(c[1]), "+f"(c[2]), "+f"(c[3])
        : "r"(a[0]), "r"(a[1]), "r"(a[2]), "r"(a[3]), "r"(b[0]), "r"(b[1]));
}

__device__ __forceinline__ void gridbar() {
    __syncthreads();
    if (threadIdx.x == 0) {
        __threadfence();
        unsigned old = atomicAdd(&g_bar_count, 1u);
        if ((old % GRID) == (GRID - 1u)) {
            atomicAdd(&g_bar_gen, 1u);
        } else {
            unsigned target = old / GRID + 1u;
            while ((int)(*(volatile unsigned*)&g_bar_gen - target) < 0) __nanosleep(32);
        }
        __threadfence();
    }
    __syncthreads();
}

extern __shared__ char dsm[];

__global__ void __launch_bounds__(NTHR, 1)
stackrnn_kernel(const float* __restrict__ x, const float* __restrict__ h0,
                const float* __restrict__ c0, const float* __restrict__ stack0,
                const float* __restrict__ W_ih, const float* __restrict__ W_hh,
                const float* __restrict__ b_ih, const float* __restrict__ b_hh,
                const float* __restrict__ A_w, const float* __restrict__ A_b,
                const float* __restrict__ D_w, const float* __restrict__ D_b,
                float* __restrict__ out) {
    const int tid = threadIdx.x;
    const int cta = blockIdx.x;
    const int warp = tid >> 5, lane = tid & 31;
    const uint32_t smem_base = smem_u32(dsm);

    float* outs = out;
    float* out_hn = out + (size_t)Sx * Bx * Hx;
    float* out_cn = out_hn + (size_t)Bx * Hx;
    float* out_st = out_cn + (size_t)Bx * Hx;

    // P1 tile mapping: 2 M-tiles (128 batches) x 64 N-tiles (16 units * 4 gates)
    const int mt = cta & 1;
    const int nt = cta >> 1;
    const int row0 = mt * 128;
    const int u0 = nt * 16;
    // 4x4 warp grid over 128x64: per-warp 32 rows x 16 cols
    const int wm = warp & 3, wn = warp >> 2;
    const int m_base = wm * 32, n_base = wn * 16;
    const int gi = lane >> 2, tg = lane & 3;

    // =============== prologue: pre-round x, h0, top; pack W ===============
    {
        // x -> g_xr (rounded), grid-stride float4
        const float4* xs = (const float4*)x;
        float4* xd = (float4*)g_xr;
        for (int i = cta * NTHR + tid; i < (Sx * Bx * Ix) / 4; i += GRID * NTHR) {
            float4 v = __ldg(xs + i);
            v.x = rndtf(v.x); v.y = rndtf(v.y); v.z = rndtf(v.z); v.w = rndtf(v.w);
            xd[i] = v;
        }
        // h0 -> g_hr[0]
        for (int i = cta * NTHR + tid; i < Bx * Hx; i += GRID * NTHR)
            g_hr[0][i] = rndtf(__ldg(h0 + i));
        // stack0 top -> g_top
        for (int i = cta * NTHR + tid; i < Bx * SWx; i += GRID * NTHR) {
            int b = i >> 8, col = i & 255;
            g_top[i] = rndtf(__ldg(stack0 + (size_t)b * SDx * SWx + col));
        }
        // W pack: row pr = nt2*64 + n  ->  src row (n>>4)*1024 + nt2*16 + (n&15)
        int pr = cta * 32 + (tid >> 4);
        int t16 = tid & 15;
        int n = pr & 63, nt2 = pr >> 6;
        int r = ((n >> 4) << 10) + nt2 * 16 + (n & 15);
        float* dst = g_Wp + (size_t)pr * KTOT;
#pragma unroll 4
        for (int c = 0; c < 24; c++) {
            int k = t16 * 96 + c * 4;
            float4 v = (k < 512)
                ? __ldg((const float4*)(W_ih + (size_t)r * 512 + k))
                : __ldg((const float4*)(W_hh + (size_t)r * 1024 + (k - 512)));
            v.x = rndtf(v.x); v.y = rndtf(v.y); v.z = rndtf(v.z); v.w = rndtf(v.w);
            *(float4*)(dst + k) = v;
        }
    }
    gridbar();

    for (int t = 0; t < Sx; ++t) {
        const float* hcur = g_hr[t & 1];
        const float* stk_r = (t == 0) ? stack0 : g_stack[t & 1];

        // =================== P1: gate GEMM (cp.async 3-stage) + fused LSTM ===================
        float acc[2][2][4];
#pragma unroll
        for (int a = 0; a < 2; a++)
#pragma unroll
            for (int b = 0; b < 2; b++)
#pragma unroll
                for (int c = 0; c < 4; c++) acc[a][b][c] = 0.f;

        auto issueCp = [&](int kc) {
            uint32_t base = smem_base + (kc % 3) * STAGE_BYTES;
            int k0 = kc * 32;
#pragma unroll
            for (int i = 0; i < 2; i++) {   // A granules: e in [0,1024)
                int e = tid + i * NTHR;
                int m = e >> 3, c4 = e & 7;
                int b = row0 + m;
                int k = k0 + c4 * 4;
                const float* src;
                if (k < 256)      src = g_xr + ((size_t)t * Bx + b) * Ix + k;
                else if (k < 512) src = g_top + (size_t)b * SWx + (k - 256);
                else              src = hcur + (size_t)b * Hx + (k - 512);
                CP16(base + m * 144 + c4 * 16, src);
            }
            {   // B granules: e in [1024,1536)
                int e = tid + 1024 - NTHR;  // i==2 slot: tid+1024 -> e-1024 = tid+512... 
                int n2 = (tid + 512) >> 3, c4 = (tid + 512) & 7;  // e = tid+1024, e-1024 = tid+512? NO
                (void)e;
                // e = tid + 2*NTHR = tid+1024 ; B index = e-1024 = tid
                n2 = tid >> 3; c4 = tid & 7;
                const float* src = g_Wp + (size_t)(nt * 64 + n2) * KTOT + k0 + c4 * 4;
                CP16(base + 18432 + n2 * 144 + c4 * 16, src);
            }
            CP_COMMIT();
        };

        issueCp(0);
        issueCp(1);
        for (int kc = 0; kc < NCH1; kc++) {
            CP_WAIT1();
            __syncthreads();
            if (kc + 2 < NCH1) issueCp(kc + 2); else CP_COMMIT();
            const float* bA = (const float*)(dsm + (kc % 3) * STAGE_BYTES);
            const float* bB = bA + 128 * 36;
#pragma unroll
            for (int kk = 0; kk < 4; kk++) {
                const int kb = kk * 8;
                unsigned af[2][4], bf[2][2];
#pragma unroll
                for (int mi = 0; mi < 2; mi++) {
                    int r0 = m_base + mi * 16 + gi;
                    af[mi][0] = __float_as_uint(bA[r0 * 36 + kb + tg]);
                    af[mi][1] = __float_as_uint(bA[(r0 + 8) * 36 + kb + tg]);
                    af[mi][2] = __float_as_uint(bA[r0 * 36 + kb + 4 + tg]);
                    af[mi][3] = __float_as_uint(bA[(r0 + 8) * 36 + kb + 4 + tg]);
                }
#pragma unroll
                for (int ni = 0; ni < 2; ni++) {
                    int c0i = n_base + ni * 8 + gi;
                    bf[ni][0] = __float_as_uint(bB[c0i * 36 + kb + tg]);
                    bf[ni][1] = __float_as_uint(bB[c0i * 36 + kb + 4 + tg]);
                }
#pragma unroll
                for (int mi = 0; mi < 2; mi++)
#pragma unroll
                    for (int ni = 0; ni < 2; ni++) mma_tf32(acc[mi][ni], af[mi], bf[ni]);
            }
        }
        // stage gates (128 x 64, pad 68) into smem (stage-0 region is free)
        {
            float* gates = (float*)dsm;
#pragma unroll
            for (int mi = 0; mi < 2; mi++)
#pragma unroll
                for (int ni = 0; ni < 2; ni++) {
                    int row = m_base + mi * 16 + gi;
                    int coln = n_base + ni * 8 + tg * 2;
                    gates[row * 68 + coln] = acc[mi][ni][0];
                    gates[row * 68 + coln + 1] = acc[mi][ni][1];
                    gates[(row + 8) * 68 + coln] = acc[mi][ni][2];
                    gates[(row + 8) * 68 + coln + 1] = acc[mi][ni][3];
                }
        }
        __syncthreads();
        // fused LSTM pointwise: 2048 (b,u) pairs, 4 per thread
        {
            const float* gates = (const float*)dsm;
            float* hw = g_hr[(t + 1) & 1];
#pragma unroll
            for (int ii = 0; ii < 4; ii++) {
                int e = tid + ii * NTHR;
                int arow = e >> 4, up = e & 15;
                int u = u0 + up;
                int b = row0 + arow;
                float iv = gates[arow * 68 + up] + __ldg(b_ih + u) + __ldg(b_hh + u);
                float fv = gates[arow * 68 + 16 + up] + __ldg(b_ih + 1024 + u) + __ldg(b_hh + 1024 + u);
                float gv = gates[arow * 68 + 32 + up] + __ldg(b_ih + 2048 + u) + __ldg(b_hh + 2048 + u);
                float ov = gates[arow * 68 + 48 + up] + __ldg(b_ih + 3072 + u) + __ldg(b_hh + 3072 + u);
                float cold = (t == 0) ? __ldg(c0 + (size_t)b * Hx + u) : g_c[(size_t)b * Hx + u];
                float cn = sigf(fv) * cold + sigf(iv) * tanhf(gv);
                float hn = sigf(ov) * tanhf(cn);
                g_c[(size_t)b * Hx + u] = cn;
                outs[(size_t)t * Bx * Hx + (size_t)b * Hx + u] = hn;
                hw[(size_t)b * Hx + u] = rndtf(hn);
            }
        }
        gridbar();

        // =================== P2: D-GEMM (threads 0-255) || controls (warps 8-15) ===================
        const float* ht = outs + (size_t)t * Bx * Hx;
        if (tid < 256) {
            float* hs = (float*)dsm;              // [64][33]
            float* dws = hs + 64 * 33;            // [16][68]
            const int mtile = cta >> 4;           // 8 x 32 batches
            const int ntile = cta & 15;           // 16 x 16 cols
            const int xr = tid & 31, yr = tid >> 5;
            float a0 = 0.f, a1 = 0.f;
            for (int kc2 = 0; kc2 < Hx; kc2 += 64) {
#pragma unroll
                for (int ii = 0; ii < 2; ii++) {
                    int e = tid + ii * 256;
                    int r = e >> 4, c4 = e & 15;
                    int k = c4 * 4;
                    float4 v = __ldcg((const float4*)(ht + (size_t)(mtile * 32 + r) * Hx + kc2 + k));
                    hs[(k + 0) * 33 + r] = v.x;
                    hs[(k + 1) * 33 + r] = v.y;
                    hs[(k + 2) * 33 + r] = v.z;
                    hs[(k + 3) * 33 + r] = v.w;
                }
                {
                    int r = tid >> 4, c4 = tid & 15;
                    float4 v = __ldg((const float4*)(D_w + (size_t)(ntile * 16 + r) * Hx + kc2 + c4 * 4));
                    float* dd = &dws[r * 68 + c4 * 4];
                    dd[0] = v.x; dd[1] = v.y; dd[2] = v.z; dd[3] = v.w;
                }
                asm volatile("bar.sync 1, 256;" ::: "memory");
#pragma unroll
                for (int k = 0; k < 64; k++) {
                    float hv = hs[k * 33 + xr];
                    a0 += hv * dws[yr * 68 + k];
                    a1 += hv * dws[(yr + 8) * 68 + k];
                }
                asm volatile("bar.sync 1, 256;" ::: "memory");
            }
            int b = mtile * 32 + xr;
            int j0 = ntile * 16 + yr, j1 = j0 + 8;
            g_d[(size_t)b * SWx + j0] = tanhf(a0 + __ldg(D_b + j0));
            g_d[(size_t)b * SWx + j1] = tanhf(a1 + __ldg(D_b + j1));
        } else if (cta < 32) {   // controls: warps 8..15, one batch each
            int b2 = cta * 8 + (warp - 8);
            const float* hb = ht + (size_t)b2 * Hx;
            float s0 = 0.f, s1 = 0.f, s2 = 0.f;
            for (int k = lane; k < Hx; k += 32) {
                float hv = __ldcg(hb + k);
                s0 += hv * __ldg(A_w + k);
                s1 += hv * __ldg(A_w + Hx + k);
                s2 += hv * __ldg(A_w + 2 * Hx + k);
            }
#pragma unroll
            for (int o = 16; o > 0; o >>= 1) {
                s0 += __shfl_xor_sync(0xffffffffu, s0, o);
                s1 += __shfl_xor_sync(0xffffffffu, s1, o);
                s2 += __shfl_xor_sync(0xffffffffu, s2, o);
            }
            if (lane == 0) {
                s0 += __ldg(A_b + 0); s1 += __ldg(A_b + 1); s2 += __ldg(A_b + 2);
                float mx = fmaxf(s0, fmaxf(s1, s2));
                float e0 = expf(s0 - mx), e1 = expf(s1 - mx), e2 = expf(s2 - mx);
                float inv = 1.f / (e0 + e1 + e2);
                g_ctl[b2 * 4 + 0] = e0 * inv;
                g_ctl[b2 * 4 + 1] = e1 * inv;
                g_ctl[b2 * 4 + 2] = e2 * inv;
            }
        }
        gridbar();

        // =================== P3: stack blend (+ rounded top, final copies) ===================
        {
            float* wst = (t == Sx - 1) ? out_st : g_stack[(t + 1) & 1];
            int b = cta * 2 + (tid >> 8);
            int col = tid & 255;
            float push = __ldcg(&g_ctl[b * 4 + 0]);
            float pop = __ldcg(&g_ctl[b * 4 + 1]);
            float noop = __ldcg(&g_ctl[b * 4 + 2]);
            float dv = __ldcg(&g_d[(size_t)b * SWx + col]);
            const float* sp = stk_r + (size_t)b * SDx * SWx + col;
            float* dp = wst + (size_t)b * SDx * SWx + col;
            float prev = dv;
            float cur = __ldcg(sp);
#pragma unroll 5
            for (int i = 0; i < SDx; i++) {
                float nxt = (i < SDx - 1) ? __ldcg(sp + (size_t)(i + 1) * SWx) : 0.f;
                float val = noop * cur + push * prev + pop * nxt;
                dp[(size_t)i * SWx] = val;
                if (i == 0) g_top[(size_t)b * SWx + col] = rndtf(val);
                prev = cur;
                cur = nxt;
            }
            if (t == Sx - 1) {
                const float* hlast = outs + (size_t)(Sx - 1) * Bx * Hx;
                for (int idx = cta * NTHR + tid; idx < Bx * Hx; idx += GRID * NTHR) {
                    out_hn[idx] = __ldcg(hlast + idx);
                    out_cn[idx] = __ldcg(&g_c[idx]);
                }
            }
        }
        gridbar();
    }
}

extern "C" void kernel_launch(void* const* d_in, const int* in_sizes, int n_in,
                              void* d_out, int out_size) {
    (void)in_sizes; (void)n_in; (void)out_size;
    cudaFuncSetAttribute(stackrnn_kernel, cudaFuncAttributeMaxDynamicSharedMemorySize, DSMEM_BYTES);
    stackrnn_kernel<<<GRID, NTHR, DSMEM_BYTES>>>(
        (const float*)d_in[0], (const float*)d_in[1], (const float*)d_in[2],
        (const float*)d_in[3], (const float*)d_in[4], (const float*)d_in[5],
        (const float*)d_in[6], (const float*)d_in[7], (const float*)d_in[8],
        (const float*)d_in[9], (const float*)d_in[10], (const float*)d_in[11],
        (float*)d_out);
}

// round 10
// speedup vs baseline: 1.7145x; 1.0736x over previous
#include <cuda_runtime.h>
#include <math.h>
#include <stdint.h>

#define Sx 512
#define Bx 256
#define Ix 256
#define Hx 1024
#define SWx 256
#define SDx 100
#define KTOT 1536
#define GRID 128
#define NTHR 512
#define NCH1 48
#define NSTAGE 6
#define STAGE_BYTES 27648        // A 128x36f + B 64x36f
#define DSMEM_BYTES (NSTAGE * STAGE_BYTES + 256)

// ---------------- persistent device state ----------------
__device__ float g_xr[(size_t)Sx * Bx * Ix];      // tf32-rounded x
__device__ float g_Wp[(size_t)4096 * KTOT];       // packed+rounded W (tile-ordered rows)
__device__ float g_hr[2][(size_t)Bx * Hx];        // rounded h ping-pong
__device__ float g_top[(size_t)Bx * SWx];         // rounded stack top
__device__ float g_c[(size_t)Bx * Hx];
__device__ float g_stack[2][(size_t)Bx * SDx * SWx];
__device__ float g_d[(size_t)Bx * SWx];
__device__ float g_ctl[Bx * 4];
__device__ unsigned g_bar_count = 0;
__device__ unsigned g_bar_gen = 0;

// ---------------- helpers ----------------
__device__ __forceinline__ float sigf(float x) { return 1.0f / (1.0f + expf(-x)); }
__device__ __forceinline__ float rndtf(float x) {
    unsigned r;
    asm("cvt.rna.tf32.f32 %0, %1;" : "=r"(r) : "f"(x));
    return __uint_as_float(r);
}
__device__ __forceinline__ uint32_t smem_u32(const void* p) {
    uint32_t a;
    asm("{ .reg .u64 t; cvta.to.shared.u64 t, %1; cvt.u32.u64 %0, t; }" : "=r"(a) : "l"(p));
    return a;
}
#define CP16(dst, src) \
    asm volatile("cp.async.cg.shared.global [%0], [%1], 16;" :: "r"(dst), "l"(src) : "memory")
#define CP_COMMIT() asm volatile("cp.async.commit_group;" ::: "memory")
#define CP_WAIT2()  asm volatile("cp.async.wait_group 2;" ::: "memory")
#define CP_WAIT0()  asm volatile("cp.async.wait_group 0;" ::: "memory")

__device__ __forceinline__ void mma_tf32(float* c, const unsigned* a, const unsigned* b) {
    asm volatile(
        "mma.sync.aligned.m16n8k8.row.col.f32.tf32.tf32.f32 "
        "{%0,%1,%2,%3},{%4,%5,%6,%7},{%8,%9},{%0,%1,%2,%3};"
        : "+f"(c[0]), "+f"(c[1]), "+f"(c[2]), "+f"(c[3])
        : "r"(a[0]), "r"(a[1]), "r"(a[2]), "r"(a[3]), "r"(b[0]), "r"(b[1]));
}

__device__ __forceinline__ void gridbar() {
    __syncthreads();
    if (threadIdx.x == 0) {
        __threadfence();
        unsigned old = atomicAdd(&g_bar_count, 1u);
        if ((old % GRID) == (GRID - 1u)) {
            atomicAdd(&g_bar_gen, 1u);
        } else {
            unsigned target = old / GRID + 1u;
            while ((int)(*(volatile unsigned*)&g_bar_gen - target) < 0) __nanosleep(32);
        }
        __threadfence();
    }
    __syncthreads();
}

extern __shared__ char dsm[];

__global__ void __launch_bounds__(NTHR, 1)
stackrnn_kernel(const float* __restrict__ x, const float* __restrict__ h0,
                const float* __restrict__ c0, const float* __restrict__ stack0,
                const float* __restrict__ W_ih, const float* __restrict__ W_hh,
                const float* __restrict__ b_ih, const float* __restrict__ b_hh,
                const float* __restrict__ A_w, const float* __restrict__ A_b,
                const float* __restrict__ D_w, const float* __restrict__ D_b,
                float* __restrict__ out) {
    const int tid = threadIdx.x;
    const int cta = blockIdx.x;
    const int warp = tid >> 5, lane = tid & 31;
    const uint32_t smem_base = smem_u32(dsm);

    float* outs = out;
    float* out_hn = out + (size_t)Sx * Bx * Hx;
    float* out_cn = out_hn + (size_t)Bx * Hx;
    float* out_st = out_cn + (size_t)Bx * Hx;

    // P1 tile mapping: 2 M-tiles (128 batches) x 64 N-tiles (16 units * 4 gates)
    const int mt = cta & 1;
    const int nt = cta >> 1;
    const int row0 = mt * 128;
    const int u0 = nt * 16;
    // 4x4 warp grid over 128x64: per-warp 32 rows x 16 cols
    const int wm = warp & 3, wn = warp >> 2;
    const int m_base = wm * 32, n_base = wn * 16;
    const int gi = lane >> 2, tg = lane & 3;

    // =============== prologue: pre-round x, h0, top; pack W ===============
    {
        const float4* xs = (const float4*)x;
        float4* xd = (float4*)g_xr;
        for (int i = cta * NTHR + tid; i < (Sx * Bx * Ix) / 4; i += GRID * NTHR) {
            float4 v = __ldg(xs + i);
            v.x = rndtf(v.x); v.y = rndtf(v.y); v.z = rndtf(v.z); v.w = rndtf(v.w);
            xd[i] = v;
        }
        for (int i = cta * NTHR + tid; i < Bx * Hx; i += GRID * NTHR)
            g_hr[0][i] = rndtf(__ldg(h0 + i));
        for (int i = cta * NTHR + tid; i < Bx * SWx; i += GRID * NTHR) {
            int b = i >> 8, col = i & 255;
            g_top[i] = rndtf(__ldg(stack0 + (size_t)b * SDx * SWx + col));
        }
        // W pack: row pr = nt2*64 + n  ->  src row (n>>4)*1024 + nt2*16 + (n&15)
        int pr = cta * 32 + (tid >> 4);
        int t16 = tid & 15;
        int n = pr & 63, nt2 = pr >> 6;
        int r = ((n >> 4) << 10) + nt2 * 16 + (n & 15);
        float* dst = g_Wp + (size_t)pr * KTOT;
#pragma unroll 4
        for (int c = 0; c < 24; c++) {
            int k = t16 * 96 + c * 4;
            float4 v = (k < 512)
                ? __ldg((const float4*)(W_ih + (size_t)r * 512 + k))
                : __ldg((const float4*)(W_hh + (size_t)r * 1024 + (k - 512)));
            v.x = rndtf(v.x); v.y = rndtf(v.y); v.z = rndtf(v.z); v.w = rndtf(v.w);
            *(float4*)(dst + k) = v;
        }
    }
    gridbar();

    for (int t = 0; t < Sx; ++t) {
        const float* hcur = g_hr[t & 1];
        const float* stk_r = (t == 0) ? stack0 : g_stack[t & 1];

        // =================== P1: gate GEMM (6-stage cp.async, 2 chunks/sync) ===================
        float acc[2][2][4];
#pragma unroll
        for (int a = 0; a < 2; a++)
#pragma unroll
            for (int b = 0; b < 2; b++)
#pragma unroll
                for (int c = 0; c < 4; c++) acc[a][b][c] = 0.f;

        auto issueCp = [&](int kc) {
            uint32_t base = smem_base + (kc % NSTAGE) * STAGE_BYTES;
            int k0 = kc * 32;
#pragma unroll
            for (int i = 0; i < 2; i++) {   // A granules
                int e = tid + i * NTHR;
                int m = e >> 3, c4 = e & 7;
                int b = row0 + m;
                int k = k0 + c4 * 4;
                const float* src;
                if (k < 256)      src = g_xr + ((size_t)t * Bx + b) * Ix + k;
                else if (k < 512) src = g_top + (size_t)b * SWx + (k - 256);
                else              src = hcur + (size_t)b * Hx + (k - 512);
                CP16(base + m * 144 + c4 * 16, src);
            }
            {   // B granule
                int n2 = tid >> 3, c4 = tid & 7;
                CP16(base + 18432 + n2 * 144 + c4 * 16,
                     g_Wp + (size_t)(nt * 64 + n2) * KTOT + k0 + c4 * 4);
            }
            CP_COMMIT();
        };

        auto consume = [&](int kc) {
            const float* bA = (const float*)(dsm + (kc % NSTAGE) * STAGE_BYTES);
            const float* bB = bA + 128 * 36;
#pragma unroll
            for (int kk = 0; kk < 4; kk++) {
                const int kb = kk * 8;
                unsigned af[2][4], bf[2][2];
#pragma unroll
                for (int mi = 0; mi < 2; mi++) {
                    int r0 = m_base + mi * 16 + gi;
                    af[mi][0] = __float_as_uint(bA[r0 * 36 + kb + tg]);
                    af[mi][1] = __float_as_uint(bA[(r0 + 8) * 36 + kb + tg]);
                    af[mi][2] = __float_as_uint(bA[r0 * 36 + kb + 4 + tg]);
                    af[mi][3] = __float_as_uint(bA[(r0 + 8) * 36 + kb + 4 + tg]);
                }
#pragma unroll
                for (int ni = 0; ni < 2; ni++) {
                    int c0i = n_base + ni * 8 + gi;
                    bf[ni][0] = __float_as_uint(bB[c0i * 36 + kb + tg]);
                    bf[ni][1] = __float_as_uint(bB[c0i * 36 + kb + 4 + tg]);
                }
#pragma unroll
                for (int mi = 0; mi < 2; mi++)
#pragma unroll
                    for (int ni = 0; ni < 2; ni++) mma_tf32(acc[mi][ni], af[mi], bf[ni]);
            }
        };

        issueCp(0); issueCp(1); issueCp(2); issueCp(3);
        for (int kp = 0; kp < NCH1; kp += 2) {
            if (kp + 2 < NCH1) { CP_WAIT2(); } else { CP_WAIT0(); }
            __syncthreads();
            if (kp + 4 < NCH1) { issueCp(kp + 4); issueCp(kp + 5); }
            consume(kp);
            consume(kp + 1);
        }
        // stage gates (128 x 64, pad 68) into smem (stage region is free)
        {
            float* gates = (float*)dsm;
#pragma unroll
            for (int mi = 0; mi < 2; mi++)
#pragma unroll
                for (int ni = 0; ni < 2; ni++) {
                    int row = m_base + mi * 16 + gi;
                    int coln = n_base + ni * 8 + tg * 2;
                    gates[row * 68 + coln] = acc[mi][ni][0];
                    gates[row * 68 + coln + 1] = acc[mi][ni][1];
                    gates[(row + 8) * 68 + coln] = acc[mi][ni][2];
                    gates[(row + 8) * 68 + coln + 1] = acc[mi][ni][3];
                }
        }
        __syncthreads();
        // fused LSTM pointwise: 2048 (b,u) pairs, 4 per thread
        {
            const float* gates = (const float*)dsm;
            float* hw = g_hr[(t + 1) & 1];
#pragma unroll
            for (int ii = 0; ii < 4; ii++) {
                int e = tid + ii * NTHR;
                int arow = e >> 4, up = e & 15;
                int u = u0 + up;
                int b = row0 + arow;
                float iv = gates[arow * 68 + up] + __ldg(b_ih + u) + __ldg(b_hh + u);
                float fv = gates[arow * 68 + 16 + up] + __ldg(b_ih + 1024 + u) + __ldg(b_hh + 1024 + u);
                float gv = gates[arow * 68 + 32 + up] + __ldg(b_ih + 2048 + u) + __ldg(b_hh + 2048 + u);
                float ov = gates[arow * 68 + 48 + up] + __ldg(b_ih + 3072 + u) + __ldg(b_hh + 3072 + u);
                float cold = (t == 0) ? __ldg(c0 + (size_t)b * Hx + u) : g_c[(size_t)b * Hx + u];
                float cn = sigf(fv) * cold + sigf(iv) * tanhf(gv);
                float hn = sigf(ov) * tanhf(cn);
                g_c[(size_t)b * Hx + u] = cn;
                outs[(size_t)t * Bx * Hx + (size_t)b * Hx + u] = hn;
                hw[(size_t)b * Hx + u] = rndtf(hn);
            }
        }
        gridbar();

        // ====== P2: D-GEMM (threads 0-255, reg-pipelined dbl buffer) || controls (warps 8-15) ======
        const float* ht = outs + (size_t)t * Bx * Hx;
        if (tid < 256) {
            const int mtile = cta >> 4;           // 8 x 32 batches
            const int ntile = cta & 15;           // 16 x 16 cols
            const int xr = tid & 31, yr = tid >> 5;
            const int fr = tid >> 4, fc4 = tid & 15;   // fetch mapping
            float a0 = 0.f, a1 = 0.f;
            float4 hv4[2], dv4;

            auto p2fetch = [&](int c) {
                int kc2 = c * 64;
#pragma unroll
                for (int ii = 0; ii < 2; ii++) {
                    int e = tid + ii * 256;
                    int r = e >> 4, c4 = e & 15;
                    hv4[ii] = __ldcg((const float4*)(ht + (size_t)(mtile * 32 + r) * Hx + kc2 + c4 * 4));
                }
                dv4 = __ldg((const float4*)(D_w + (size_t)(ntile * 16 + fr) * Hx + kc2 + fc4 * 4));
            };
            auto p2store = [&](int c) {
                float* hs = (float*)(dsm + (c & 1) * 12800);
                float* dws = hs + 64 * 33;
#pragma unroll
                for (int ii = 0; ii < 2; ii++) {
                    int e = tid + ii * 256;
                    int r = e >> 4, c4 = e & 15;
                    int k = c4 * 4;
                    hs[(k + 0) * 33 + r] = hv4[ii].x;
                    hs[(k + 1) * 33 + r] = hv4[ii].y;
                    hs[(k + 2) * 33 + r] = hv4[ii].z;
                    hs[(k + 3) * 33 + r] = hv4[ii].w;
                }
                float* dd = &dws[fr * 68 + fc4 * 4];
                dd[0] = dv4.x; dd[1] = dv4.y; dd[2] = dv4.z; dd[3] = dv4.w;
            };

            p2fetch(0);
            for (int c = 0; c < 16; c++) {
                p2store(c);
                if (c < 15) p2fetch(c + 1);
                asm volatile("bar.sync 1, 256;" ::: "memory");
                const float* hs = (const float*)(dsm + (c & 1) * 12800);
                const float* dws = hs + 64 * 33;
#pragma unroll
                for (int k = 0; k < 64; k++) {
                    float hv = hs[k * 33 + xr];
                    a0 += hv * dws[yr * 68 + k];
                    a1 += hv * dws[(yr + 8) * 68 + k];
                }
            }
            int b = mtile * 32 + xr;
            int j0 = ntile * 16 + yr, j1 = j0 + 8;
            g_d[(size_t)b * SWx + j0] = tanhf(a0 + __ldg(D_b + j0));
            g_d[(size_t)b * SWx + j1] = tanhf(a1 + __ldg(D_b + j1));
        } else if (cta < 32) {   // controls: warps 8..15, one batch each
            int b2 = cta * 8 + (warp - 8);
            const float* hb = ht + (size_t)b2 * Hx;
            float s0 = 0.f, s1 = 0.f, s2 = 0.f;
            for (int k = lane; k < Hx; k += 32) {
                float hv = __ldcg(hb + k);
                s0 += hv * __ldg(A_w + k);
                s1 += hv * __ldg(A_w + Hx + k);
                s2 += hv * __ldg(A_w + 2 * Hx + k);
            }
#pragma unroll
            for (int o = 16; o > 0; o >>= 1) {
                s0 += __shfl_xor_sync(0xffffffffu, s0, o);
                s1 += __shfl_xor_sync(0xffffffffu, s1, o);
                s2 += __shfl_xor_sync(0xffffffffu, s2, o);
            }
            if (lane == 0) {
                s0 += __ldg(A_b + 0); s1 += __ldg(A_b + 1); s2 += __ldg(A_b + 2);
                float mx = fmaxf(s0, fmaxf(s1, s2));
                float e0 = expf(s0 - mx), e1 = expf(s1 - mx), e2 = expf(s2 - mx);
                float inv = 1.f / (e0 + e1 + e2);
                g_ctl[b2 * 4 + 0] = e0 * inv;
                g_ctl[b2 * 4 + 1] = e1 * inv;
                g_ctl[b2 * 4 + 2] = e2 * inv;
            }
        }
        gridbar();

        // =================== P3: stack blend (+ rounded top, final copies) ===================
        {
            float* wst = (t == Sx - 1) ? out_st : g_stack[(t + 1) & 1];
            int b = cta * 2 + (tid >> 8);
            int col = tid & 255;
            float push = __ldcg(&g_ctl[b * 4 + 0]);
            float pop = __ldcg(&g_ctl[b * 4 + 1]);
            float noop = __ldcg(&g_ctl[b * 4 + 2]);
            float dv = __ldcg(&g_d[(size_t)b * SWx + col]);
            const float* sp = stk_r + (size_t)b * SDx * SWx + col;
            float* dp = wst + (size_t)b * SDx * SWx + col;
            float prev = dv;
            float cur = __ldcg(sp);
#pragma unroll 5
            for (int i = 0; i < SDx; i++) {
                float nxt = (i < SDx - 1) ? __ldcg(sp + (size_t)(i + 1) * SWx) : 0.f;
                float val = noop * cur + push * prev + pop * nxt;
                dp[(size_t)i * SWx] = val;
                if (i == 0) g_top[(size_t)b * SWx + col] = rndtf(val);
                prev = cur;
                cur = nxt;
            }
            if (t == Sx - 1) {
                const float* hlast = outs + (size_t)(Sx - 1) * Bx * Hx;
                for (int idx = cta * NTHR + tid; idx < Bx * Hx; idx += GRID * NTHR) {
                    out_hn[idx] = __ldcg(hlast + idx);
                    out_cn[idx] = __ldcg(&g_c[idx]);
                }
            }
        }
        gridbar();
    }
}

extern "C" void kernel_launch(void* const* d_in, const int* in_sizes, int n_in,
                              void* d_out, int out_size) {
    (void)in_sizes; (void)n_in; (void)out_size;
    cudaFuncSetAttribute(stackrnn_kernel, cudaFuncAttributeMaxDynamicSharedMemorySize, DSMEM_BYTES);
    stackrnn_kernel<<<GRID, NTHR, DSMEM_BYTES>>>(
        (const float*)d_in[0], (const float*)d_in[1], (const float*)d_in[2],
        (const float*)d_in[3], (const float*)d_in[4], (const float*)d_in[5],
        (const float*)d_in[6], (const float*)d_in[7], (const float*)d_in[8],
        (const float*)d_in[9], (const float*)d_in[10], (const float*)d_in[11],
        (float*)d_out);
}

// round 13
// speedup vs baseline: 2.0086x; 1.1715x over previous
#include <cuda_runtime.h>
#include <math.h>
#include <stdint.h>

#define Sx 512
#define Bx 256
#define Ix 256
#define Hx 1024
#define SWx 256
#define SDx 100
#define GRID 128
#define NTHR 512
#define NCH1 48
#define NSTAGE 6
#define STAGE_BYTES 24576            // A 16384 + B 8192, fragment-major
#define DSMEM_BYTES (NSTAGE * STAGE_BYTES + 256)

// ---------------- persistent device state (fragment-major where noted) ----------------
__device__ float g_xA[(size_t)Sx * 2 * 8 * 4096];     // x permuted: [t][mt][chunk0-7][4096]
__device__ float g_Wp[(size_t)64 * 48 * 2048];        // W permuted: [nt][chunk][2048]
__device__ float g_hrP[2][(size_t)2 * 32 * 4096];     // h permuted ping-pong: [mt][chunk][4096]
__device__ float g_topP[(size_t)2 * 8 * 4096];        // stack top permuted: [mt][chunk][4096]
__device__ float g_c[(size_t)Bx * Hx];
__device__ float g_stack[2][(size_t)Bx * SDx * SWx];
__device__ float g_d[(size_t)Bx * SWx];
__device__ float g_ctl[Bx * 4];
__device__ unsigned g_bar_count = 0;
__device__ unsigned g_bar_gen = 0;

// ---------------- helpers ----------------
__device__ __forceinline__ float sigf(float x) { return 1.0f / (1.0f + expf(-x)); }
__device__ __forceinline__ float rndtf(float x) {
    unsigned r;
    asm("cvt.rna.tf32.f32 %0, %1;" : "=r"(r) : "f"(x));
    return __uint_as_float(r);
}
__device__ __forceinline__ uint32_t smem_u32(const void* p) {
    uint32_t a;
    asm("{ .reg .u64 t; cvta.to.shared.u64 t, %1; cvt.u32.u64 %0, t; }" : "=r"(a) : "l"(p));
    return a;
}
// in-chunk scalar offset for A-side fragment-major layout (m in [0,128), kl in [0,32))
__device__ __forceinline__ int aoff(int m, int kl) {
    return (((m >> 5) * 2 + ((m >> 4) & 1)) * 4 + (kl >> 3)) * 128
         + ((m & 7) * 4 + (kl & 3)) * 4 + ((m >> 3) & 1) + 2 * ((kl >> 2) & 1);
}
#define CP16(dst, src) \
    asm volatile("cp.async.cg.shared.global [%0], [%1], 16;" :: "r"(dst), "l"(src) : "memory")
#define CP_COMMIT() asm volatile("cp.async.commit_group;" ::: "memory")
#define CP_WAIT2()  asm volatile("cp.async.wait_group 2;" ::: "memory")
#define CP_WAIT0()  asm volatile("cp.async.wait_group 0;" ::: "memory")

__device__ __forceinline__ void mma_tf32(float* c, const unsigned* a, const unsigned* b) {
    asm volatile(
        "mma.sync.aligned.m16n8k8.row.col.f32.tf32.tf32.f32 "
        "{%0,%1,%2,%3},{%4,%5,%6,%7},{%8,%9},{%0,%1,%2,%3};"
        : "+f"(c[0]), "+f"(c[1]), "+f"(c[2]), "+f"(c[3])
        : "r"(a[0]), "r"(a[1]), "r"(a[2]), "r"(a[3]), "r"(b[0]), "r"(b[1]));
}

__device__ __forceinline__ void gridbar() {
    __syncthreads();
    if (threadIdx.x == 0) {
        __threadfence();
        unsigned old = atomicAdd(&g_bar_count, 1u);
        if ((old % GRID) == (GRID - 1u)) {
            atomicAdd(&g_bar_gen, 1u);
        } else {
            unsigned target = old / GRID + 1u;
            while ((int)(*(volatile unsigned*)&g_bar_gen - target) < 0) {
                __nanosleep(32);
            }
        }
        __threadfence();
    }
    __syncthreads();
}

extern __shared__ char dsm[];

__global__ void __launch_bounds__(NTHR, 1)
stackrnn_kernel(const float* __restrict__ x, const float* __restrict__ h0,
                const float* __restrict__ c0, const float* __restrict__ stack0,
                const float* __restrict__ W_ih, const float* __restrict__ W_hh,
                const float* __restrict__ b_ih, const float* __restrict__ b_hh,
                const float* __restrict__ A_w, const float* __restrict__ A_b,
                const float* __restrict__ D_w, const float* __restrict__ D_b,
                float* __restrict__ out) {
    const int tid = threadIdx.x;
    const int cta = blockIdx.x;
    const int warp = tid >> 5, lane = tid & 31;
    const uint32_t smem_base = smem_u32(dsm);

    float* outs = out;
    float* out_hn = out + (size_t)Sx * Bx * Hx;
    float* out_cn = out_hn + (size_t)Bx * Hx;
    float* out_st = out_cn + (size_t)Bx * Hx;

    // P1 tile mapping: 2 M-tiles (128 batches) x 64 N-tiles (16 units * 4 gates)
    const int mt = cta & 1;
    const int nt = cta >> 1;
    const int row0 = mt * 128;
    const int u0 = nt * 16;
    // MMA warps 0-7: 4x2 grid of 32x32 tiles over the 128x64 CTA tile
    const int wm = warp & 3, wn = (warp >> 2) & 1;
    const int m_base = wm * 32, n_base = wn * 32;
    const int gi = lane >> 2, tg = lane & 3;

    // =============== prologue: build permuted buffers ===============
    {
        // --- x -> g_xA (fragment-major quads) ---
        for (size_t q = (size_t)cta * NTHR + tid; q < (size_t)Sx * 2 * 8 * 1024;
             q += (size_t)GRID * NTHR) {
            int qin = (int)(q & 1023);
            int chunk = (int)((q >> 10) & 7);
            int mtq = (int)((q >> 13) & 1);
            int tq = (int)(q >> 14);
            int ln = qin & 31, kk = (qin >> 5) & 3, mi = (qin >> 7) & 1, wmq = qin >> 8;
            int b0 = mtq * 128 + wmq * 32 + mi * 16 + (ln >> 2);
            int k0 = chunk * 32 + kk * 8 + (ln & 3);
            const float* xs = x + ((size_t)tq * Bx + b0) * Ix + k0;
            float4 v;
            v.x = rndtf(xs[0]);
            v.y = rndtf(xs[(size_t)8 * Ix]);
            v.z = rndtf(xs[4]);
            v.w = rndtf(xs[(size_t)8 * Ix + 4]);
            ((float4*)g_xA)[q] = v;
        }
        // --- h0 -> g_hrP[0] ---
        for (int q = cta * NTHR + tid; q < 2 * 32 * 1024; q += GRID * NTHR) {
            int qin = q & 1023;
            int ch = (q >> 10) & 31;
            int mtq = q >> 15;
            int ln = qin & 31, kk = (qin >> 5) & 3, mi = (qin >> 7) & 1, wmq = qin >> 8;
            int b0 = mtq * 128 + wmq * 32 + mi * 16 + (ln >> 2);
            int uq = ch * 32 + kk * 8 + (ln & 3);
            const float* hs = h0 + (size_t)b0 * Hx + uq;
            float4 v;
            v.x = rndtf(hs[0]);
            v.y = rndtf(hs[(size_t)8 * Hx]);
            v.z = rndtf(hs[4]);
            v.w = rndtf(hs[(size_t)8 * Hx + 4]);
            ((float4*)g_hrP[0])[q] = v;
        }
        // --- stack0 top -> g_topP ---
        for (int q = cta * NTHR + tid; q < 2 * 8 * 1024; q += GRID * NTHR) {
            int qin = q & 1023;
            int ch = (q >> 10) & 7;
            int mtq = q >> 13;
            int ln = qin & 31, kk = (qin >> 5) & 3, mi = (qin >> 7) & 1, wmq = qin >> 8;
            int b0 = mtq * 128 + wmq * 32 + mi * 16 + (ln >> 2);
            int col0 = ch * 32 + kk * 8 + (ln & 3);
            const float* ss = stack0 + (size_t)b0 * SDx * SWx + col0;
            float4 v;
            v.x = rndtf(ss[0]);
            v.y = rndtf(ss[(size_t)8 * SDx * SWx]);
            v.z = rndtf(ss[4]);
            v.w = rndtf(ss[(size_t)8 * SDx * SWx + 4]);
            ((float4*)g_topP)[q] = v;
        }
        // --- W -> g_Wp (fragment-major quads) ---
        for (int q = cta * NTHR + tid; q < 64 * 48 * 512; q += GRID * NTHR) {
            int qb = q & 511;
            int chunk = (q >> 9) % 48;
            int ntq = q / (48 * 512);
            int ln = qb & 31, h2 = (qb >> 5) & 1, kk = (qb >> 6) & 3, wnq = qb >> 8;
            int giq = ln >> 2, tgq = ln & 3;
            int n0 = wnq * 32 + (2 * h2) * 8 + giq;     // jn=0
            int n1 = n0 + 8;                             // jn=1
            int k0 = chunk * 32 + kk * 8 + tgq;
            int r0 = ((n0 >> 4) << 10) + ntq * 16 + (n0 & 15);
            int r1 = ((n1 >> 4) << 10) + ntq * 16 + (n1 & 15);
            auto fetch = [&](int r, int k) -> float {
                return (k < 512) ? __ldg(W_ih + (size_t)r * 512 + k)
                                 : __ldg(W_hh + (size_t)r * 1024 + (k - 512));
            };
            float4 v;
            v.x = rndtf(fetch(r0, k0));
            v.y = rndtf(fetch(r0, k0 + 4));
            v.z = rndtf(fetch(r1, k0));
            v.w = rndtf(fetch(r1, k0 + 4));
            ((float4*)g_Wp)[q] = v;
        }
    }
    gridbar();

    // cp.async: straight linear copy, layouts match
    auto issueCp = [&](int kc, int tt) {
        uint32_t base = smem_base + (kc % NSTAGE) * STAGE_BYTES;
        const float* asrc;
        if (kc < 8)       asrc = g_xA + (((size_t)tt * 2 + mt) * 8 + kc) * 4096;
        else if (kc < 16) asrc = g_topP + ((size_t)mt * 8 + (kc - 8)) * 4096;
        else              asrc = g_hrP[tt & 1] + ((size_t)mt * 32 + (kc - 16)) * 4096;
#pragma unroll
        for (int i = 0; i < 2; i++) {
            int ga = tid + i * NTHR;
            CP16(base + ga * 16, asrc + ga * 4);
        }
        CP16(base + 16384 + tid * 16, g_Wp + ((size_t)nt * 48 + kc) * 2048 + tid * 4);
        CP_COMMIT();
    };

    for (int t = 0; t < Sx; ++t) {
        const float* stk_r = (t == 0) ? stack0 : g_stack[t & 1];

        // =================== P1: gate GEMM (6-stage cp.async, fragment-major) ===================
        float acc[2][4][4];
#pragma unroll
        for (int a = 0; a < 2; a++)
#pragma unroll
            for (int b = 0; b < 4; b++)
#pragma unroll
                for (int c = 0; c < 4; c++) acc[a][b][c] = 0.f;

        auto consume = [&](int kc) {
            const float4* bA = (const float4*)(dsm + (kc % NSTAGE) * STAGE_BYTES);
            const float4* bB = (const float4*)(dsm + (kc % NSTAGE) * STAGE_BYTES + 16384);
#pragma unroll
            for (int kk = 0; kk < 4; kk++) {
                float4 qa0 = bA[((wm * 2 + 0) * 4 + kk) * 32 + lane];
                float4 qa1 = bA[((wm * 2 + 1) * 4 + kk) * 32 + lane];
                float4 qb0 = bB[((wn * 4 + kk) * 2 + 0) * 32 + lane];
                float4 qb1 = bB[((wn * 4 + kk) * 2 + 1) * 32 + lane];
                unsigned af0[4] = {__float_as_uint(qa0.x), __float_as_uint(qa0.y),
                                   __float_as_uint(qa0.z), __float_as_uint(qa0.w)};
                unsigned af1[4] = {__float_as_uint(qa1.x), __float_as_uint(qa1.y),
                                   __float_as_uint(qa1.z), __float_as_uint(qa1.w)};
                unsigned bf[4][2] = {
                    {__float_as_uint(qb0.x), __float_as_uint(qb0.y)},
                    {__float_as_uint(qb0.z), __float_as_uint(qb0.w)},
                    {__float_as_uint(qb1.x), __float_as_uint(qb1.y)},
                    {__float_as_uint(qb1.z), __float_as_uint(qb1.w)}};
#pragma unroll
                for (int ni = 0; ni < 4; ni++) {
                    mma_tf32(acc[0][ni], af0, bf[ni]);
                    mma_tf32(acc[1][ni], af1, bf[ni]);
                }
            }
        };

        issueCp(0, t); issueCp(1, t); issueCp(2, t); issueCp(3, t);
        for (int kp = 0; kp < NCH1; kp += 2) {
            if (kp + 2 < NCH1) { CP_WAIT2(); } else { CP_WAIT0(); }
            __syncthreads();
            if (kp + 4 < NCH1) { issueCp(kp + 4, t); issueCp(kp + 5, t); }
            if (warp < 8) {
                consume(kp);
                consume(kp + 1);
            }
        }
        // stage gates (128 x 64, pad 68) into smem
        if (warp < 8) {
            float* gates = (float*)dsm;
#pragma unroll
            for (int mi = 0; mi < 2; mi++)
#pragma unroll
                for (int ni = 0; ni < 4; ni++) {
                    int row = m_base + mi * 16 + gi;
                    int coln = n_base + ni * 8 + tg * 2;
                    gates[row * 68 + coln] = acc[mi][ni][0];
                    gates[row * 68 + coln + 1] = acc[mi][ni][1];
                    gates[(row + 8) * 68 + coln] = acc[mi][ni][2];
                    gates[(row + 8) * 68 + coln + 1] = acc[mi][ni][3];
                }
        }
        __syncthreads();
        // fused LSTM pointwise: 2048 (b,u) pairs, 4 per thread; h scattered to permuted buffer
        {
            const float* gates = (const float*)dsm;
            float* hw = g_hrP[(t + 1) & 1];
#pragma unroll
            for (int ii = 0; ii < 4; ii++) {
                int e = tid + ii * NTHR;
                int arow = e >> 4, up = e & 15;
                int u = u0 + up;
                int b = row0 + arow;
                float iv = gates[arow * 68 + up] + __ldg(b_ih + u) + __ldg(b_hh + u);
                float fv = gates[arow * 68 + 16 + up] + __ldg(b_ih + 1024 + u) + __ldg(b_hh + 1024 + u);
                float gv = gates[arow * 68 + 32 + up] + __ldg(b_ih + 2048 + u) + __ldg(b_hh + 2048 + u);
                float ov = gates[arow * 68 + 48 + up] + __ldg(b_ih + 3072 + u) + __ldg(b_hh + 3072 + u);
                float cold = (t == 0) ? __ldg(c0 + (size_t)b * Hx + u) : g_c[(size_t)b * Hx + u];
                float cn = sigf(fv) * cold + sigf(iv) * tanhf(gv);
                float hn = sigf(ov) * tanhf(cn);
                g_c[(size_t)b * Hx + u] = cn;
                outs[(size_t)t * Bx * Hx + (size_t)b * Hx + u] = hn;
                hw[((size_t)mt * 32 + (u >> 5)) * 4096 + aoff(arow, u & 31)] = rndtf(hn);
            }
        }
        gridbar();

        // ====== P2: D-GEMM (threads 0-255, reg-pipelined dbl buffer) || controls (warps 8-15) ======
        const float* ht = outs + (size_t)t * Bx * Hx;
        if (tid < 256) {
            const int mtile = cta >> 4;           // 8 x 32 batches
            const int ntile = cta & 15;           // 16 x 16 cols
            const int xr = tid & 31, yr = tid >> 5;
            const int fr = tid >> 4, fc4 = tid & 15;
            float a0 = 0.f, a1 = 0.f;
            float4 hv4[2], dv4;

            auto p2fetch = [&](int c) {
                int kc2 = c * 64;
#pragma unroll
                for (int ii = 0; ii < 2; ii++) {
                    int e = tid + ii * 256;
                    int r = e >> 4, c4 = e & 15;
                    hv4[ii] = __ldcg((const float4*)(ht + (size_t)(mtile * 32 + r) * Hx + kc2 + c4 * 4));
                }
                dv4 = __ldg((const float4*)(D_w + (size_t)(ntile * 16 + fr) * Hx + kc2 + fc4 * 4));
            };
            auto p2store = [&](int c) {
                float* hs = (float*)(dsm + (c & 1) * 12800);
                float* dws = hs + 64 * 33;
#pragma unroll
                for (int ii = 0; ii < 2; ii++) {
                    int e = tid + ii * 256;
                    int r = e >> 4, c4 = e & 15;
                    int k = c4 * 4;
                    hs[(k + 0) * 33 + r] = hv4[ii].x;
                    hs[(k + 1) * 33 + r] = hv4[ii].y;
                    hs[(k + 2) * 33 + r] = hv4[ii].z;
                    hs[(k + 3) * 33 + r] = hv4[ii].w;
                }
                float* dd = &dws[fr * 68 + fc4 * 4];
                dd[0] = dv4.x; dd[1] = dv4.y; dd[2] = dv4.z; dd[3] = dv4.w;
            };

            p2fetch(0);
            for (int c = 0; c < 16; c++) {
                p2store(c);
                if (c < 15) p2fetch(c + 1);
                asm volatile("bar.sync 1, 256;" ::: "memory");
                const float* hs = (const float*)(dsm + (c & 1) * 12800);
                const float* dws = hs + 64 * 33;
#pragma unroll
                for (int k = 0; k < 64; k++) {
                    float hv = hs[k * 33 + xr];
                    a0 += hv * dws[yr * 68 + k];
                    a1 += hv * dws[(yr + 8) * 68 + k];
                }
            }
            int b = mtile * 32 + xr;
            int j0 = ntile * 16 + yr, j1 = j0 + 8;
            g_d[(size_t)b * SWx + j0] = tanhf(a0 + __ldg(D_b + j0));
            g_d[(size_t)b * SWx + j1] = tanhf(a1 + __ldg(D_b + j1));
        } else if (cta < 32) {   // controls: warps 8..15, one batch each
            int b2 = cta * 8 + (warp - 8);
            const float* hb = ht + (size_t)b2 * Hx;
            float s0 = 0.f, s1 = 0.f, s2 = 0.f;
            for (int k = lane; k < Hx; k += 32) {
                float hv = __ldcg(hb + k);
                s0 += hv * __ldg(A_w + k);
                s1 += hv * __ldg(A_w + Hx + k);
                s2 += hv * __ldg(A_w + 2 * Hx + k);
            }
#pragma unroll
            for (int o = 16; o > 0; o >>= 1) {
                s0 += __shfl_xor_sync(0xffffffffu, s0, o);
                s1 += __shfl_xor_sync(0xffffffffu, s1, o);
                s2 += __shfl_xor_sync(0xffffffffu, s2, o);
            }
            if (lane == 0) {
                s0 += __ldg(A_b + 0); s1 += __ldg(A_b + 1); s2 += __ldg(A_b + 2);
                float mx = fmaxf(s0, fmaxf(s1, s2));
                float e0 = expf(s0 - mx), e1 = expf(s1 - mx), e2 = expf(s2 - mx);
                float inv = 1.f / (e0 + e1 + e2);
                g_ctl[b2 * 4 + 0] = e0 * inv;
                g_ctl[b2 * 4 + 1] = e1 * inv;
                g_ctl[b2 * 4 + 2] = e2 * inv;
            }
        }
        gridbar();

        // =================== P3: stack blend (+ permuted top, final copies) ===================
        {
            float* wst = (t == Sx - 1) ? out_st : g_stack[(t + 1) & 1];
            int b = cta * 2 + (tid >> 8);
            int col = tid & 255;
            float push = __ldcg(&g_ctl[b * 4 + 0]);
            float pop = __ldcg(&g_ctl[b * 4 + 1]);
            float noop = __ldcg(&g_ctl[b * 4 + 2]);
            float dv = __ldcg(&g_d[(size_t)b * SWx + col]);
            const float* sp = stk_r + (size_t)b * SDx * SWx + col;
            float* dp = wst + (size_t)b * SDx * SWx + col;
            float prev = dv;
            float cur = __ldcg(sp);
#pragma unroll 5
            for (int i = 0; i < SDx; i++) {
                float nxt = (i < SDx - 1) ? __ldcg(sp + (size_t)(i + 1) * SWx) : 0.f;
                float val = noop * cur + push * prev + pop * nxt;
                dp[(size_t)i * SWx] = val;
                if (i == 0) {
                    g_topP[((size_t)(b >> 7) * 8 + (col >> 5)) * 4096 + aoff(b & 127, col & 31)]
                        = rndtf(val);
                }
                prev = cur;
                cur = nxt;
            }
            if (t == Sx - 1) {
                const float* hlast = outs + (size_t)(Sx - 1) * Bx * Hx;
                for (int idx = cta * NTHR + tid; idx < Bx * Hx; idx += GRID * NTHR) {
                    out_hn[idx] = __ldcg(hlast + idx);
                    out_cn[idx] = __ldcg(&g_c[idx]);
                }
            }
        }
        gridbar();
    }
}

extern "C" void kernel_launch(void* const* d_in, const int* in_sizes, int n_in,
                              void* d_out, int out_size) {
    (void)in_sizes; (void)n_in; (void)out_size;
    cudaFuncSetAttribute(stackrnn_kernel, cudaFuncAttributeMaxDynamicSharedMemorySize, DSMEM_BYTES);
    stackrnn_kernel<<<GRID, NTHR, DSMEM_BYTES>>>(
        (const float*)d_in[0], (const float*)d_in[1], (const float*)d_in[2],
        (const float*)d_in[3], (const float*)d_in[4], (const float*)d_in[5],
        (const float*)d_in[6], (const float*)d_in[7], (const float*)d_in[8],
        (const float*)d_in[9], (const float*)d_in[10], (const float*)d_in[11],
        (float*)d_out);
}

// round 14
// speedup vs baseline: 2.1264x; 1.0586x over previous
#include <cuda_runtime.h>
#include <math.h>
#include <stdint.h>

#define Sx 512
#define Bx 256
#define Ix 256
#define Hx 1024
#define SWx 256
#define SDx 100
#define GRID 128
#define NTHR 512
#define NCH1 48
#define NSTAGE 6
#define STAGE_BYTES 24576            // A 16384 + B 8192, fragment-major
#define DSMEM_BYTES (NSTAGE * STAGE_BYTES + 256)

// ---------------- persistent device state (fragment-major where noted) ----------------
__device__ float g_xA[(size_t)Sx * 2 * 8 * 4096];     // x permuted: [t][mt][chunk0-7][4096]
__device__ float g_Wp[(size_t)64 * 48 * 2048];        // W permuted: [nt][chunk][2048]
__device__ float g_Dwp[(size_t)16 * 32 * 512];        // D_w permuted: [jt][chunk][512]
__device__ float g_hrP[2][(size_t)2 * 32 * 4096];     // h permuted ping-pong: [mt][chunk][4096]
__device__ float g_topP[(size_t)2 * 8 * 4096];        // stack top permuted: [mt][chunk][4096]
__device__ float g_c[(size_t)Bx * Hx];
__device__ float g_stack[2][(size_t)Bx * SDx * SWx];
__device__ float g_d[(size_t)Bx * SWx];
__device__ float g_ctl[Bx * 4];
__device__ unsigned g_bar_count = 0;
__device__ unsigned g_bar_gen = 0;

// ---------------- helpers ----------------
__device__ __forceinline__ float sigf(float x) { return 1.0f / (1.0f + expf(-x)); }
__device__ __forceinline__ float rndtf(float x) {
    unsigned r;
    asm("cvt.rna.tf32.f32 %0, %1;" : "=r"(r) : "f"(x));
    return __uint_as_float(r);
}
__device__ __forceinline__ uint32_t smem_u32(const void* p) {
    uint32_t a;
    asm("{ .reg .u64 t; cvta.to.shared.u64 t, %1; cvt.u32.u64 %0, t; }" : "=r"(a) : "l"(p));
    return a;
}
// in-chunk scalar offset for A-side fragment-major layout (m in [0,128), kl in [0,32))
__device__ __forceinline__ int aoff(int m, int kl) {
    return (((m >> 5) * 2 + ((m >> 4) & 1)) * 4 + (kl >> 3)) * 128
         + ((m & 7) * 4 + (kl & 3)) * 4 + ((m >> 3) & 1) + 2 * ((kl >> 2) & 1);
}
#define CP16(dst, src) \
    asm volatile("cp.async.cg.shared.global [%0], [%1], 16;" :: "r"(dst), "l"(src) : "memory")
#define CP_COMMIT() asm volatile("cp.async.commit_group;" ::: "memory")
#define CP_WAIT2()  asm volatile("cp.async.wait_group 2;" ::: "memory")
#define CP_WAIT0()  asm volatile("cp.async.wait_group 0;" ::: "memory")

__device__ __forceinline__ void mma_tf32(float* c, const unsigned* a, const unsigned* b) {
    asm volatile(
        "mma.sync.aligned.m16n8k8.row.col.f32.tf32.tf32.f32 "
        "{%0,%1,%2,%3},{%4,%5,%6,%7},{%8,%9},{%0,%1,%2,%3};"
        : "+f"(c[0]), "+f"(c[1]), "+f"(c[2]), "+f"(c[3])
        : "r"(a[0]), "r"(a[1]), "r"(a[2]), "r"(a[3]), "r"(b[0]), "r"(b[1]));
}

__device__ __forceinline__ void gridbar() {
    __syncthreads();
    if (threadIdx.x == 0) {
        __threadfence();
        unsigned old = atomicAdd(&g_bar_count, 1u);
        if ((old % GRID) == (GRID - 1u)) {
            atomicAdd(&g_bar_gen, 1u);
        } else {
            unsigned target = old / GRID + 1u;
            while ((int)(*(volatile unsigned*)&g_bar_gen - target) < 0) {
                __nanosleep(32);
            }
        }
        __threadfence();
    }
    __syncthreads();
}

extern __shared__ char dsm[];

__global__ void __launch_bounds__(NTHR, 1)
stackrnn_kernel(const float* __restrict__ x, const float* __restrict__ h0,
                const float* __restrict__ c0, const float* __restrict__ stack0,
                const float* __restrict__ W_ih, const float* __restrict__ W_hh,
                const float* __restrict__ b_ih, const float* __restrict__ b_hh,
                const float* __restrict__ A_w, const float* __restrict__ A_b,
                const float* __restrict__ D_w, const float* __restrict__ D_b,
                float* __restrict__ out) {
    const int tid = threadIdx.x;
    const int cta = blockIdx.x;
    const int warp = tid >> 5, lane = tid & 31;
    const uint32_t smem_base = smem_u32(dsm);

    float* outs = out;
    float* out_hn = out + (size_t)Sx * Bx * Hx;
    float* out_cn = out_hn + (size_t)Bx * Hx;
    float* out_st = out_cn + (size_t)Bx * Hx;

    // P1 tile mapping: 2 M-tiles (128 batches) x 64 N-tiles (16 units * 4 gates)
    const int mt = cta & 1;
    const int nt = cta >> 1;
    const int row0 = mt * 128;
    const int u0 = nt * 16;
    // MMA warps 0-7: 4x2 grid of 32x32 tiles over the 128x64 CTA tile
    const int wm = warp & 3, wn = (warp >> 2) & 1;
    const int m_base = wm * 32, n_base = wn * 32;
    const int gi = lane >> 2, tg = lane & 3;

    // =============== prologue: build permuted buffers ===============
    {
        // --- x -> g_xA (fragment-major quads) ---
        for (size_t q = (size_t)cta * NTHR + tid; q < (size_t)Sx * 2 * 8 * 1024;
             q += (size_t)GRID * NTHR) {
            int qin = (int)(q & 1023);
            int chunk = (int)((q >> 10) & 7);
            int mtq = (int)((q >> 13) & 1);
            int tq = (int)(q >> 14);
            int ln = qin & 31, kk = (qin >> 5) & 3, mi = (qin >> 7) & 1, wmq = qin >> 8;
            int b0 = mtq * 128 + wmq * 32 + mi * 16 + (ln >> 2);
            int k0 = chunk * 32 + kk * 8 + (ln & 3);
            const float* xs = x + ((size_t)tq * Bx + b0) * Ix + k0;
            float4 v;
            v.x = rndtf(xs[0]);
            v.y = rndtf(xs[(size_t)8 * Ix]);
            v.z = rndtf(xs[4]);
            v.w = rndtf(xs[(size_t)8 * Ix + 4]);
            ((float4*)g_xA)[q] = v;
        }
        // --- h0 -> g_hrP[0] ---
        for (int q = cta * NTHR + tid; q < 2 * 32 * 1024; q += GRID * NTHR) {
            int qin = q & 1023;
            int ch = (q >> 10) & 31;
            int mtq = q >> 15;
            int ln = qin & 31, kk = (qin >> 5) & 3, mi = (qin >> 7) & 1, wmq = qin >> 8;
            int b0 = mtq * 128 + wmq * 32 + mi * 16 + (ln >> 2);
            int uq = ch * 32 + kk * 8 + (ln & 3);
            const float* hs = h0 + (size_t)b0 * Hx + uq;
            float4 v;
            v.x = rndtf(hs[0]);
            v.y = rndtf(hs[(size_t)8 * Hx]);
            v.z = rndtf(hs[4]);
            v.w = rndtf(hs[(size_t)8 * Hx + 4]);
            ((float4*)g_hrP[0])[q] = v;
        }
        // --- stack0 top -> g_topP ---
        for (int q = cta * NTHR + tid; q < 2 * 8 * 1024; q += GRID * NTHR) {
            int qin = q & 1023;
            int ch = (q >> 10) & 7;
            int mtq = q >> 13;
            int ln = qin & 31, kk = (qin >> 5) & 3, mi = (qin >> 7) & 1, wmq = qin >> 8;
            int b0 = mtq * 128 + wmq * 32 + mi * 16 + (ln >> 2);
            int col0 = ch * 32 + kk * 8 + (ln & 3);
            const float* ss = stack0 + (size_t)b0 * SDx * SWx + col0;
            float4 v;
            v.x = rndtf(ss[0]);
            v.y = rndtf(ss[(size_t)8 * SDx * SWx]);
            v.z = rndtf(ss[4]);
            v.w = rndtf(ss[(size_t)8 * SDx * SWx + 4]);
            ((float4*)g_topP)[q] = v;
        }
        // --- W -> g_Wp (fragment-major quads) ---
        for (int q = cta * NTHR + tid; q < 64 * 48 * 512; q += GRID * NTHR) {
            int qb = q & 511;
            int chunk = (q >> 9) % 48;
            int ntq = q / (48 * 512);
            int ln = qb & 31, h2 = (qb >> 5) & 1, kk = (qb >> 6) & 3, wnq = qb >> 8;
            int giq = ln >> 2, tgq = ln & 3;
            int n0 = wnq * 32 + (2 * h2) * 8 + giq;     // jn=0
            int n1 = n0 + 8;                             // jn=1
            int k0 = chunk * 32 + kk * 8 + tgq;
            int r0 = ((n0 >> 4) << 10) + ntq * 16 + (n0 & 15);
            int r1 = ((n1 >> 4) << 10) + ntq * 16 + (n1 & 15);
            auto fetch = [&](int r, int k) -> float {
                return (k < 512) ? __ldg(W_ih + (size_t)r * 512 + k)
                                 : __ldg(W_hh + (size_t)r * 1024 + (k - 512));
            };
            float4 v;
            v.x = rndtf(fetch(r0, k0));
            v.y = rndtf(fetch(r0, k0 + 4));
            v.z = rndtf(fetch(r1, k0));
            v.w = rndtf(fetch(r1, k0 + 4));
            ((float4*)g_Wp)[q] = v;
        }
        // --- D_w -> g_Dwp (B-fragment quads: [jt][chunk][ (wn*2+kp)*32+lane ]) ---
        for (int q = cta * NTHR + tid; q < 16 * 32 * 128; q += GRID * NTHR) {
            int qb = q & 127;
            int chunk = (q >> 7) & 31;
            int jt = q >> 12;
            int ln = qb & 31, kp = (qb >> 5) & 1, wnq = qb >> 6;
            int j = jt * 16 + wnq * 8 + (ln >> 2);
            int k = chunk * 32 + kp * 16 + (ln & 3);
            const float* ds = D_w + (size_t)j * Hx + k;
            float4 v;
            v.x = rndtf(ds[0]);
            v.y = rndtf(ds[4]);
            v.z = rndtf(ds[8]);
            v.w = rndtf(ds[12]);
            ((float4*)g_Dwp)[q] = v;
        }
    }
    gridbar();

    // cp.async: straight linear copy, layouts match
    auto issueCp = [&](int kc, int tt) {
        uint32_t base = smem_base + (kc % NSTAGE) * STAGE_BYTES;
        const float* asrc;
        if (kc < 8)       asrc = g_xA + (((size_t)tt * 2 + mt) * 8 + kc) * 4096;
        else if (kc < 16) asrc = g_topP + ((size_t)mt * 8 + (kc - 8)) * 4096;
        else              asrc = g_hrP[tt & 1] + ((size_t)mt * 32 + (kc - 16)) * 4096;
#pragma unroll
        for (int i = 0; i < 2; i++) {
            int ga = tid + i * NTHR;
            CP16(base + ga * 16, asrc + ga * 4);
        }
        CP16(base + 16384 + tid * 16, g_Wp + ((size_t)nt * 48 + kc) * 2048 + tid * 4);
        CP_COMMIT();
    };

    for (int t = 0; t < Sx; ++t) {
        const float* stk_r = (t == 0) ? stack0 : g_stack[t & 1];

        // =================== P1: gate GEMM (6-stage cp.async, fragment-major) ===================
        float acc[2][4][4];
#pragma unroll
        for (int a = 0; a < 2; a++)
#pragma unroll
            for (int b = 0; b < 4; b++)
#pragma unroll
                for (int c = 0; c < 4; c++) acc[a][b][c] = 0.f;

        auto consume = [&](int kc) {
            const float4* bA = (const float4*)(dsm + (kc % NSTAGE) * STAGE_BYTES);
            const float4* bB = (const float4*)(dsm + (kc % NSTAGE) * STAGE_BYTES + 16384);
#pragma unroll
            for (int kk = 0; kk < 4; kk++) {
                float4 qa0 = bA[((wm * 2 + 0) * 4 + kk) * 32 + lane];
                float4 qa1 = bA[((wm * 2 + 1) * 4 + kk) * 32 + lane];
                float4 qb0 = bB[((wn * 4 + kk) * 2 + 0) * 32 + lane];
                float4 qb1 = bB[((wn * 4 + kk) * 2 + 1) * 32 + lane];
                unsigned af0[4] = {__float_as_uint(qa0.x), __float_as_uint(qa0.y),
                                   __float_as_uint(qa0.z), __float_as_uint(qa0.w)};
                unsigned af1[4] = {__float_as_uint(qa1.x), __float_as_uint(qa1.y),
                                   __float_as_uint(qa1.z), __float_as_uint(qa1.w)};
                unsigned bf[4][2] = {
                    {__float_as_uint(qb0.x), __float_as_uint(qb0.y)},
                    {__float_as_uint(qb0.z), __float_as_uint(qb0.w)},
                    {__float_as_uint(qb1.x), __float_as_uint(qb1.y)},
                    {__float_as_uint(qb1.z), __float_as_uint(qb1.w)}};
#pragma unroll
                for (int ni = 0; ni < 4; ni++) {
                    mma_tf32(acc[0][ni], af0, bf[ni]);
                    mma_tf32(acc[1][ni], af1, bf[ni]);
                }
            }
        };

        issueCp(0, t); issueCp(1, t); issueCp(2, t); issueCp(3, t);
        for (int kp = 0; kp < NCH1; kp += 2) {
            if (kp + 2 < NCH1) { CP_WAIT2(); } else { CP_WAIT0(); }
            __syncthreads();
            if (kp + 4 < NCH1) { issueCp(kp + 4, t); issueCp(kp + 5, t); }
            if (warp < 8) {
                consume(kp);
                consume(kp + 1);
            }
        }
        // stage gates (128 x 64, pad 68) into smem
        if (warp < 8) {
            float* gates = (float*)dsm;
#pragma unroll
            for (int mi = 0; mi < 2; mi++)
#pragma unroll
                for (int ni = 0; ni < 4; ni++) {
                    int row = m_base + mi * 16 + gi;
                    int coln = n_base + ni * 8 + tg * 2;
                    gates[row * 68 + coln] = acc[mi][ni][0];
                    gates[row * 68 + coln + 1] = acc[mi][ni][1];
                    gates[(row + 8) * 68 + coln] = acc[mi][ni][2];
                    gates[(row + 8) * 68 + coln + 1] = acc[mi][ni][3];
                }
        }
        __syncthreads();
        // fused LSTM pointwise: 2048 (b,u) pairs, 4 per thread; h scattered to permuted buffer
        {
            const float* gates = (const float*)dsm;
            float* hw = g_hrP[(t + 1) & 1];
#pragma unroll
            for (int ii = 0; ii < 4; ii++) {
                int e = tid + ii * NTHR;
                int arow = e >> 4, up = e & 15;
                int u = u0 + up;
                int b = row0 + arow;
                float iv = gates[arow * 68 + up] + __ldg(b_ih + u) + __ldg(b_hh + u);
                float fv = gates[arow * 68 + 16 + up] + __ldg(b_ih + 1024 + u) + __ldg(b_hh + 1024 + u);
                float gv = gates[arow * 68 + 32 + up] + __ldg(b_ih + 2048 + u) + __ldg(b_hh + 2048 + u);
                float ov = gates[arow * 68 + 48 + up] + __ldg(b_ih + 3072 + u) + __ldg(b_hh + 3072 + u);
                float cold = (t == 0) ? __ldg(c0 + (size_t)b * Hx + u) : g_c[(size_t)b * Hx + u];
                float cn = sigf(fv) * cold + sigf(iv) * tanhf(gv);
                float hn = sigf(ov) * tanhf(cn);
                g_c[(size_t)b * Hx + u] = cn;
                outs[(size_t)t * Bx * Hx + (size_t)b * Hx + u] = hn;
                hw[((size_t)mt * 32 + (u >> 5)) * 4096 + aoff(arow, u & 31)] = rndtf(hn);
            }
        }
        gridbar();

        // ====== P2: tensor D-GEMM (CTAs 0-31, no smem/syncs) || controls (CTAs 32-47) ======
        if (cta < 32) {
            const int mt2 = cta & 1, jt = cta >> 1;
            if (warp < 8) {
                const float4* Ab = (const float4*)(g_hrP[(t + 1) & 1]) + (size_t)mt2 * 32 * 1024;
                const float4* Bb = (const float4*)g_Dwp + (size_t)jt * 32 * 128;
                float acc2[2][4];
#pragma unroll
                for (int ni = 0; ni < 2; ni++)
#pragma unroll
                    for (int c = 0; c < 4; c++) acc2[ni][c] = 0.f;
#pragma unroll 2
                for (int ch = 0; ch < 32; ch++) {
                    float4 qa[4], qb[2][2];
#pragma unroll
                    for (int kk = 0; kk < 4; kk++)
                        qa[kk] = __ldcg(Ab + (size_t)ch * 1024 + (warp * 4 + kk) * 32 + lane);
#pragma unroll
                    for (int w2 = 0; w2 < 2; w2++)
#pragma unroll
                        for (int kp = 0; kp < 2; kp++)
                            qb[w2][kp] = __ldg(Bb + (size_t)ch * 128 + (w2 * 2 + kp) * 32 + lane);
#pragma unroll
                    for (int kk = 0; kk < 4; kk++) {
                        unsigned af[4] = {__float_as_uint(qa[kk].x), __float_as_uint(qa[kk].y),
                                          __float_as_uint(qa[kk].z), __float_as_uint(qa[kk].w)};
#pragma unroll
                        for (int ni = 0; ni < 2; ni++) {
                            float4 q = qb[ni][kk >> 1];
                            unsigned bf2[2];
                            if ((kk & 1) == 0) { bf2[0] = __float_as_uint(q.x); bf2[1] = __float_as_uint(q.y); }
                            else               { bf2[0] = __float_as_uint(q.z); bf2[1] = __float_as_uint(q.w); }
                            mma_tf32(acc2[ni], af, bf2);
                        }
                    }
                }
                int b = mt2 * 128 + warp * 16 + gi;
#pragma unroll
                for (int ni = 0; ni < 2; ni++) {
                    int j = jt * 16 + ni * 8 + tg * 2;
                    g_d[(size_t)b * SWx + j]       = tanhf(acc2[ni][0] + __ldg(D_b + j));
                    g_d[(size_t)b * SWx + j + 1]   = tanhf(acc2[ni][1] + __ldg(D_b + j + 1));
                    g_d[(size_t)(b + 8) * SWx + j] = tanhf(acc2[ni][2] + __ldg(D_b + j));
                    g_d[(size_t)(b + 8) * SWx + j + 1] = tanhf(acc2[ni][3] + __ldg(D_b + j + 1));
                }
            }
        } else if (cta < 48) {   // controls: warp per batch
            int b2 = (cta - 32) * 16 + warp;
            const float* hb = outs + (size_t)t * Bx * Hx + (size_t)b2 * Hx;
            float s0 = 0.f, s1 = 0.f, s2 = 0.f;
            for (int k = lane; k < Hx; k += 32) {
                float hv = __ldcg(hb + k);
                s0 += hv * __ldg(A_w + k);
                s1 += hv * __ldg(A_w + Hx + k);
                s2 += hv * __ldg(A_w + 2 * Hx + k);
            }
#pragma unroll
            for (int o = 16; o > 0; o >>= 1) {
                s0 += __shfl_xor_sync(0xffffffffu, s0, o);
                s1 += __shfl_xor_sync(0xffffffffu, s1, o);
                s2 += __shfl_xor_sync(0xffffffffu, s2, o);
            }
            if (lane == 0) {
                s0 += __ldg(A_b + 0); s1 += __ldg(A_b + 1); s2 += __ldg(A_b + 2);
                float mx = fmaxf(s0, fmaxf(s1, s2));
                float e0 = expf(s0 - mx), e1 = expf(s1 - mx), e2 = expf(s2 - mx);
                float inv = 1.f / (e0 + e1 + e2);
                g_ctl[b2 * 4 + 0] = e0 * inv;
                g_ctl[b2 * 4 + 1] = e1 * inv;
                g_ctl[b2 * 4 + 2] = e2 * inv;
            }
        }
        gridbar();

        // =================== P3: stack blend (+ permuted top, final copies) ===================
        {
            float* wst = (t == Sx - 1) ? out_st : g_stack[(t + 1) & 1];
            int b = cta * 2 + (tid >> 8);
            int col = tid & 255;
            float push = __ldcg(&g_ctl[b * 4 + 0]);
            float pop = __ldcg(&g_ctl[b * 4 + 1]);
            float noop = __ldcg(&g_ctl[b * 4 + 2]);
            float dv = __ldcg(&g_d[(size_t)b * SWx + col]);
            const float* sp = stk_r + (size_t)b * SDx * SWx + col;
            float* dp = wst + (size_t)b * SDx * SWx + col;
            float prev = dv;
            float cur = __ldcg(sp);
#pragma unroll 5
            for (int i = 0; i < SDx; i++) {
                float nxt = (i < SDx - 1) ? __ldcg(sp + (size_t)(i + 1) * SWx) : 0.f;
                float val = noop * cur + push * prev + pop * nxt;
                dp[(size_t)i * SWx] = val;
                if (i == 0) {
                    g_topP[((size_t)(b >> 7) * 8 + (col >> 5)) * 4096 + aoff(b & 127, col & 31)]
                        = rndtf(val);
                }
                prev = cur;
                cur = nxt;
            }
            if (t == Sx - 1) {
                const float* hlast = outs + (size_t)(Sx - 1) * Bx * Hx;
                for (int idx = cta * NTHR + tid; idx < Bx * Hx; idx += GRID * NTHR) {
                    out_hn[idx] = __ldcg(hlast + idx);
                    out_cn[idx] = __ldcg(&g_c[idx]);
                }
            }
        }
        gridbar();
    }
}

extern "C" void kernel_launch(void* const* d_in, const int* in_sizes, int n_in,
                              void* d_out, int out_size) {
    (void)in_sizes; (void)n_in; (void)out_size;
    cudaFuncSetAttribute(stackrnn_kernel, cudaFuncAttributeMaxDynamicSharedMemorySize, DSMEM_BYTES);
    stackrnn_kernel<<<GRID, NTHR, DSMEM_BYTES>>>(
        (const float*)d_in[0], (const float*)d_in[1], (const float*)d_in[2],
        (const float*)d_in[3], (const float*)d_in[4], (const float*)d_in[5],
        (const float*)d_in[6], (const float*)d_in[7], (const float*)d_in[8],
        (const float*)d_in[9], (const float*)d_in[10], (const float*)d_in[11],
        (float*)d_out);
}